// round 7
// baseline (speedup 1.0000x reference)
#include <cuda_runtime.h>
#include <mma.h>
#include <math.h>

using namespace nvcuda;

#define LYRS 12
#define NH 12
#define DMODEL 768
#define DHEAD 64
#define DMLP 3072
#define NVOCAB 50257
#define NVPAD 50304
#define BATCH 2
#define SEQ 1024
#define MROWS 2048

// ---- scratch (device globals; no allocation allowed) ----
__device__ float g_resid[MROWS*DMODEL];
__device__ float g_x[MROWS*DMODEL];
__device__ float g_q[MROWS*DMODEL];
__device__ float g_k[MROWS*DMODEL];
__device__ float g_v[MROWS*DMODEL];
__device__ float g_z[MROWS*DMODEL];
__device__ float g_h[MROWS*DMLP];
// repacked K-major [N][K] tf32-rounded weights
__device__ float g_bq[LYRS*DMODEL*DMODEL];
__device__ float g_bk[LYRS*DMODEL*DMODEL];
__device__ float g_bv[LYRS*DMODEL*DMODEL];
__device__ float g_bo[LYRS*DMODEL*DMODEL];
__device__ float g_bin[LYRS*DMLP*DMODEL];
__device__ float g_bout[LYRS*DMODEL*DMLP];
__device__ float g_bu[(long)NVPAD*DMODEL];

__device__ __forceinline__ float to_tf32(float x) {
    unsigned u; asm("cvt.rna.tf32.f32 %0, %1;" : "=r"(u) : "f"(x));
    return __uint_as_float(u);
}
__device__ __forceinline__ void cpa16(float* dst, const float* src) {
    unsigned d = (unsigned)__cvta_generic_to_shared(dst);
    asm volatile("cp.async.cg.shared.global [%0], [%1], 16;" :: "r"(d), "l"(src));
}

// ---- embedding ----
__global__ void embed_kernel(const int* __restrict__ tokens, const float* __restrict__ WE,
                             const float* __restrict__ Wpos, float* __restrict__ resid)
{
    int idx = blockIdx.x * blockDim.x + threadIdx.x;
    if (idx >= MROWS*DMODEL) return;
    int d = idx % DMODEL, bs = idx / DMODEL, s = bs % SEQ;
    resid[idx] = WE[(long)tokens[bs]*DMODEL + d] + Wpos[s*DMODEL + d];
}

// ---- layernorm (rounds output to tf32) ----
__global__ void layernorm_kernel(const float* __restrict__ in, const float* __restrict__ w,
                                 const float* __restrict__ b, float* __restrict__ out)
{
    __shared__ float sm[16];
    int row = blockIdx.x, tid = threadIdx.x;
    const float* x = in + (long)row * DMODEL;
    float s = 0.f, ss = 0.f;
    for (int i = tid; i < DMODEL; i += 256) { float v = x[i]; s += v; ss += v*v; }
    #pragma unroll
    for (int o = 16; o > 0; o >>= 1) {
        s  += __shfl_xor_sync(0xffffffffu, s,  o);
        ss += __shfl_xor_sync(0xffffffffu, ss, o);
    }
    if ((tid & 31) == 0) { sm[tid>>5] = s; sm[8 + (tid>>5)] = ss; }
    __syncthreads();
    if (tid < 8) {
        float a = sm[tid], c = sm[8+tid];
        #pragma unroll
        for (int o = 4; o > 0; o >>= 1) {
            a += __shfl_xor_sync(0xffu, a, o);
            c += __shfl_xor_sync(0xffu, c, o);
        }
        if (tid == 0) { sm[0] = a; sm[8] = c; }
    }
    __syncthreads();
    float mean = sm[0] * (1.f/DMODEL);
    float var  = sm[8] * (1.f/DMODEL) - mean*mean;
    float inv  = rsqrtf(var + 1e-5f);
    for (int i = tid; i < DMODEL; i += 256)
        out[(long)row*DMODEL + i] = to_tf32((x[i]-mean)*inv*w[i] + b[i]);
}

// ---- weight repack: per-head [L][H][D][DH] -> [L][h*64+e][D] (tf32) ----
__global__ void trans_head(const float* __restrict__ src, float* __restrict__ dst)
{
    __shared__ float t[32][33];
    int tx = threadIdx.x, ty = threadIdx.y;
    int d0 = blockIdx.x*32, e0 = blockIdx.y*32, lh = blockIdx.z;
    int l = lh / NH, h = lh % NH;
    const float* sp = src + (long)lh*DMODEL*DHEAD;
    float* dp = dst + (long)l*DMODEL*DMODEL;
    #pragma unroll
    for (int i = 0; i < 4; i++)
        t[ty+8*i][tx] = sp[(long)(d0+ty+8*i)*DHEAD + e0+tx];
    __syncthreads();
    #pragma unroll
    for (int i = 0; i < 4; i++)
        dp[(long)(h*64 + e0+ty+8*i)*DMODEL + d0+tx] = to_tf32(t[tx][ty+8*i]);
}

// ---- weight repack: [K,N] -> [Npad,K] transpose (tf32, zero pad) ----
__global__ void trans_kn(const float* __restrict__ src, float* __restrict__ dst,
                         int K, int N, int Npad)
{
    __shared__ float t[32][33];
    int tx = threadIdx.x, ty = threadIdx.y;
    int n0 = blockIdx.x*32, k0 = blockIdx.y*32, l = blockIdx.z;
    const float* sp = src + (long)l*K*N;
    float* dp = dst + (long)l*Npad*K;
    #pragma unroll
    for (int i = 0; i < 4; i++) {
        int n = n0+tx;
        t[ty+8*i][tx] = (n < N) ? sp[(long)(k0+ty+8*i)*N + n] : 0.f;
    }
    __syncthreads();
    #pragma unroll
    for (int i = 0; i < 4; i++)
        dp[(long)(n0+ty+8*i)*K + k0+tx] = to_tf32(t[tx][ty+8*i]);
}

// ---- wmma tf32 GEMM: C[2048,nvalid] = A[2048,K] @ B[Npad,K]^T ----
// TM x 128 block tile, BK=32, 3-stage cp.async, one sync/iter, 8 warps.
#define BKG 32
#define ALD 36
#define CLD 132

typedef wmma::fragment<wmma::matrix_a, 16,16,8, wmma::precision::tf32, wmma::row_major> AFrag;
typedef wmma::fragment<wmma::matrix_b, 16,16,8, wmma::precision::tf32, wmma::col_major> BFrag;
typedef wmma::fragment<wmma::accumulator, 16,16,8, float> CFrag;

template<int TM, bool GELU, bool RES>
__device__ __forceinline__ void gemm_core(
    const float* __restrict__ A, const float* __restrict__ B,
    const float* __restrict__ bias, const float* __restrict__ res,
    float* __restrict__ C, int K, int nvalid)
{
    extern __shared__ float smem[];
    const int STAGE = (TM+128)*ALD;
    const int MF = TM/32;                 // m-frags per warp
    int tid = threadIdx.x, wid = tid >> 5;
    int bm = blockIdx.y * TM, bn = blockIdx.x * 128;
    int wm = (wid >> 2) * (TM/2);
    int wn = (wid & 3) * 32;

    CFrag acc[TM/32][2];
    #pragma unroll
    for (int i = 0; i < MF; i++)
        #pragma unroll
        for (int j = 0; j < 2; j++) wmma::fill_fragment(acc[i][j], 0.f);

    auto loadStage = [&](int s, int it) {
        float* as = smem + s*STAGE;
        float* bs = as + TM*ALD;
        const float* Ag = A + (long)bm*K + it*BKG;
        const float* Bg = B + (long)bn*K + it*BKG;
        #pragma unroll
        for (int i = 0; i < TM/32; i++) {
            int idx = tid + 256*i;
            int row = idx >> 3, c4 = (idx & 7) << 2;
            cpa16(as + row*ALD + c4, Ag + (long)row*K + c4);
        }
        #pragma unroll
        for (int i = 0; i < 4; i++) {
            int idx = tid + 256*i;
            int row = idx >> 3, c4 = (idx & 7) << 2;
            cpa16(bs + row*ALD + c4, Bg + (long)row*K + c4);
        }
        asm volatile("cp.async.commit_group;" ::);
    };

    const int nIter = K / BKG;
    loadStage(0, 0);
    loadStage(1, 1);

    for (int it = 0; it < nIter; it++) {
        int cur = it % 3;
        if (it + 2 < nIter) asm volatile("cp.async.wait_group 1;" ::);
        else                asm volatile("cp.async.wait_group 0;" ::);
        __syncthreads();
        if (it + 2 < nIter) loadStage((it+2) % 3, it+2);

        const float* as = smem + cur*STAGE;
        const float* bs = as + TM*ALD;
        #pragma unroll
        for (int ks = 0; ks < 4; ks++) {
            AFrag af[TM/32];
            BFrag bf[2];
            #pragma unroll
            for (int mi = 0; mi < MF; mi++)
                wmma::load_matrix_sync(af[mi], as + (wm + mi*16)*ALD + ks*8, ALD);
            #pragma unroll
            for (int ni = 0; ni < 2; ni++)
                wmma::load_matrix_sync(bf[ni], bs + (wn + ni*16)*ALD + ks*8, ALD);
            #pragma unroll
            for (int mi = 0; mi < MF; mi++)
                #pragma unroll
                for (int ni = 0; ni < 2; ni++)
                    wmma::mma_sync(acc[mi][ni], af[mi], bf[ni], acc[mi][ni]);
        }
    }
    __syncthreads();

    // epilogue via smem (alias stages)
    float* Cs = smem;
    #pragma unroll
    for (int mi = 0; mi < MF; mi++)
        #pragma unroll
        for (int ni = 0; ni < 2; ni++)
            wmma::store_matrix_sync(Cs + (wm + mi*16)*CLD + wn + ni*16,
                                    acc[mi][ni], CLD, wmma::mem_row_major);
    __syncthreads();

    for (int idx = tid; idx < TM*128; idx += 256) {
        int r = idx >> 7, c = idx & 127;
        int n = bn + c;
        if (n < nvalid) {
            float v = Cs[r*CLD + c] + bias[n];
            long gr = bm + r;
            if (RES) v += res[gr*nvalid + n];
            if (GELU) {
                float t3 = v*v*v;
                v = 0.5f*v*(1.f + tanhf(0.7978845608028654f*(v + 0.044715f*t3)));
                v = to_tf32(v);
            }
            C[gr*nvalid + n] = v;
        }
    }
}

template<int TM, bool GELU, bool RES>
__global__ void __launch_bounds__(256) gemm_w(
    const float* __restrict__ A, const float* __restrict__ B,
    const float* __restrict__ bias, const float* __restrict__ res,
    float* __restrict__ C, int K, int nvalid)
{
    gemm_core<TM,GELU,RES>(A, B, bias, res, C, K, nvalid);
}

__global__ void __launch_bounds__(256) qkv_w(
    const float* __restrict__ A,
    const float* __restrict__ Bq, const float* __restrict__ Bk, const float* __restrict__ Bv,
    const float* __restrict__ bq, const float* __restrict__ bk, const float* __restrict__ bv,
    float* __restrict__ q, float* __restrict__ k, float* __restrict__ v)
{
    const float* B; const float* bias; float* C;
    int z = blockIdx.z;
    if (z == 0)      { B = Bq; bias = bq; C = q; }
    else if (z == 1) { B = Bk; bias = bk; C = k; }
    else             { B = Bv; bias = bv; C = v; }
    gemm_core<128,false,false>(A, B, bias, nullptr, C, DMODEL, DMODEL);
}

// ---- flash attention: block per (64 q-rows, h, b); 128 threads ----
// threads (r, hf): hf=0/1 computes keys [hf*16,hf*16+16) for QK, e-dims [hf*32,hf*32+32) for PV.
__global__ void __launch_bounds__(128) flash_kernel(
    const float* __restrict__ q, const float* __restrict__ k,
    const float* __restrict__ v, float* __restrict__ z)
{
    __shared__ float Qs[64][68];
    __shared__ float Ks[32][68];
    __shared__ float Vs[32][68];
    __shared__ float Ss[64][33];
    int tid = threadIdx.x;
    int r = tid & 63, hf = tid >> 6;
    int qt = blockIdx.x, h = blockIdx.y, b = blockIdx.z;
    int qi = qt*64 + r;

    // coalesced Q load: 64x64
    #pragma unroll 8
    for (int i = 0; i < 32; i++) {
        int lin = tid + 128*i;
        int row = lin >> 6, col = lin & 63;
        Qs[row][col] = q[(long)(b*SEQ + qt*64 + row)*DMODEL + h*DHEAD + col];
    }

    float o[32];
    #pragma unroll
    for (int e = 0; e < 32; e++) o[e] = 0.f;
    float m = -1e30f, l = 0.f;

    int ntiles = qt*2 + 2;
    for (int kt = 0; kt < ntiles; kt++) {
        __syncthreads();
        long kb = (long)(b*SEQ + kt*32)*DMODEL + h*DHEAD;
        #pragma unroll 4
        for (int i = 0; i < 16; i++) {
            int lin = tid + 128*i;
            int row = lin >> 6, col = lin & 63;
            Ks[row][col] = k[kb + (long)row*DMODEL + col];
            Vs[row][col] = v[kb + (long)row*DMODEL + col];
        }
        __syncthreads();
        // scores for this thread's 16 keys
        #pragma unroll
        for (int jg = 0; jg < 2; jg++) {
            float sa[8];
            #pragma unroll
            for (int i = 0; i < 8; i++) sa[i] = 0.f;
            #pragma unroll
            for (int e4 = 0; e4 < 16; e4++) {
                float4 qv = *(const float4*)&Qs[r][e4*4];
                #pragma unroll
                for (int i = 0; i < 8; i++) {
                    float4 kk = *(const float4*)&Ks[hf*16 + jg*8 + i][e4*4];
                    sa[i] += qv.x*kk.x + qv.y*kk.y + qv.z*kk.z + qv.w*kk.w;
                }
            }
            #pragma unroll
            for (int i = 0; i < 8; i++) Ss[r][hf*16 + jg*8 + i] = sa[i];
        }
        __syncthreads();
        // softmax (each half-thread redundantly, deterministic)
        float p[32];
        float tmax = -1e30f;
        #pragma unroll
        for (int j = 0; j < 32; j++) {
            int kj = kt*32 + j;
            float sv = (kj <= qi) ? Ss[r][j]*0.125f : -1e30f;
            p[j] = sv;
            tmax = fmaxf(tmax, sv);
        }
        float mn = fmaxf(m, tmax);
        float sc = __expf(m - mn);
        float ts = 0.f;
        #pragma unroll
        for (int j = 0; j < 32; j++) {
            float pj = __expf(p[j] - mn);
            p[j] = pj;
            ts += pj;
        }
        l = l*sc + ts;
        m = mn;
        #pragma unroll
        for (int e = 0; e < 32; e++) o[e] *= sc;
        // PV over this thread's 32 e-dims
        for (int j = 0; j < 32; j++) {
            float pj = p[j];
            #pragma unroll
            for (int e4 = 0; e4 < 8; e4++) {
                float4 vv = *(const float4*)&Vs[j][hf*32 + e4*4];
                o[e4*4+0] += pj*vv.x; o[e4*4+1] += pj*vv.y;
                o[e4*4+2] += pj*vv.z; o[e4*4+3] += pj*vv.w;
            }
        }
    }
    float inv = 1.f / l;
    long zrow = (long)(b*SEQ + qi)*DMODEL + h*DHEAD + hf*32;
    #pragma unroll
    for (int e = 0; e < 32; e++) z[zrow + e] = to_tf32(o[e]*inv);
}

// smem sizes (bytes)
#define SMB128 (3*(128+128)*ALD*4)   // 110592
#define SMB64  (3*(64+128)*ALD*4)    // 82944

extern "C" void kernel_launch(void* const* d_in, const int* in_sizes, int n_in,
                              void* d_out, int out_size)
{
    const int*   tokens = (const int*)  d_in[0];
    const float* W_E    = (const float*)d_in[1];
    const float* W_pos  = (const float*)d_in[2];
    const float* ln1_w  = (const float*)d_in[3];
    const float* ln1_b  = (const float*)d_in[4];
    const float* W_Q    = (const float*)d_in[5];
    const float* b_Q    = (const float*)d_in[6];
    const float* W_K    = (const float*)d_in[7];
    const float* b_K    = (const float*)d_in[8];
    const float* W_V    = (const float*)d_in[9];
    const float* b_V    = (const float*)d_in[10];
    const float* W_O    = (const float*)d_in[11];
    const float* b_O    = (const float*)d_in[12];
    const float* ln2_w  = (const float*)d_in[13];
    const float* ln2_b  = (const float*)d_in[14];
    const float* W_in   = (const float*)d_in[15];
    const float* b_in   = (const float*)d_in[16];
    const float* W_out  = (const float*)d_in[17];
    const float* b_out  = (const float*)d_in[18];
    const float* lnf_w  = (const float*)d_in[19];
    const float* lnf_b  = (const float*)d_in[20];
    const float* W_U    = (const float*)d_in[21];
    const float* b_U    = (const float*)d_in[22];
    float* out = (float*)d_out;

    float *p_resid, *p_x, *p_q, *p_k, *p_v, *p_z, *p_h;
    float *p_bq, *p_bk, *p_bv, *p_bo, *p_bin, *p_bout, *p_bu;
    cudaGetSymbolAddress((void**)&p_resid, g_resid);
    cudaGetSymbolAddress((void**)&p_x, g_x);
    cudaGetSymbolAddress((void**)&p_q, g_q);
    cudaGetSymbolAddress((void**)&p_k, g_k);
    cudaGetSymbolAddress((void**)&p_v, g_v);
    cudaGetSymbolAddress((void**)&p_z, g_z);
    cudaGetSymbolAddress((void**)&p_h, g_h);
    cudaGetSymbolAddress((void**)&p_bq, g_bq);
    cudaGetSymbolAddress((void**)&p_bk, g_bk);
    cudaGetSymbolAddress((void**)&p_bv, g_bv);
    cudaGetSymbolAddress((void**)&p_bo, g_bo);
    cudaGetSymbolAddress((void**)&p_bin, g_bin);
    cudaGetSymbolAddress((void**)&p_bout, g_bout);
    cudaGetSymbolAddress((void**)&p_bu, g_bu);

    cudaFuncSetAttribute((const void*)gemm_w<128,false,false>, cudaFuncAttributeMaxDynamicSharedMemorySize, SMB128);
    cudaFuncSetAttribute((const void*)gemm_w<128,true,false>,  cudaFuncAttributeMaxDynamicSharedMemorySize, SMB128);
    cudaFuncSetAttribute((const void*)gemm_w<64,false,true>,   cudaFuncAttributeMaxDynamicSharedMemorySize, SMB64);
    cudaFuncSetAttribute((const void*)qkv_w,                   cudaFuncAttributeMaxDynamicSharedMemorySize, SMB128);

    dim3 tb(32, 8);
    trans_head<<<dim3(24, 2, LYRS*NH), tb>>>(W_Q, p_bq);
    trans_head<<<dim3(24, 2, LYRS*NH), tb>>>(W_K, p_bk);
    trans_head<<<dim3(24, 2, LYRS*NH), tb>>>(W_V, p_bv);
    trans_kn<<<dim3(24, 24, LYRS), tb>>>(W_O, p_bo, DMODEL, DMODEL, DMODEL);
    trans_kn<<<dim3(96, 24, LYRS), tb>>>(W_in, p_bin, DMODEL, DMLP, DMLP);
    trans_kn<<<dim3(24, 96, LYRS), tb>>>(W_out, p_bout, DMLP, DMODEL, DMODEL);
    trans_kn<<<dim3(NVPAD/32, 24, 1), tb>>>(W_U, p_bu, DMODEL, NVOCAB, NVPAD);

    embed_kernel<<<(MROWS*DMODEL + 255)/256, 256>>>(tokens, W_E, W_pos, p_resid);

    for (int l = 0; l < LYRS; l++) {
        layernorm_kernel<<<MROWS, 256>>>(p_resid, ln1_w + l*DMODEL, ln1_b + l*DMODEL, p_x);

        qkv_w<<<dim3(6, 16, 3), 256, SMB128>>>(
            p_x,
            p_bq + (long)l*DMODEL*DMODEL, p_bk + (long)l*DMODEL*DMODEL, p_bv + (long)l*DMODEL*DMODEL,
            b_Q + l*DMODEL, b_K + l*DMODEL, b_V + l*DMODEL,
            p_q, p_k, p_v);

        flash_kernel<<<dim3(SEQ/64, NH, BATCH), 128>>>(p_q, p_k, p_v, p_z);

        gemm_w<64,false,true><<<dim3(6, 32), 256, SMB64>>>(
            p_z, p_bo + (long)l*DMODEL*DMODEL, b_O + l*DMODEL, p_resid, p_resid,
            DMODEL, DMODEL);

        layernorm_kernel<<<MROWS, 256>>>(p_resid, ln2_w + l*DMODEL, ln2_b + l*DMODEL, p_x);

        gemm_w<128,true,false><<<dim3(24, 16), 256, SMB128>>>(
            p_x, p_bin + (long)l*DMLP*DMODEL, b_in + l*DMLP, nullptr, p_h,
            DMODEL, DMLP);

        gemm_w<64,false,true><<<dim3(6, 32), 256, SMB64>>>(
            p_h, p_bout + (long)l*DMODEL*DMLP, b_out + l*DMODEL, p_resid, p_resid,
            DMLP, DMODEL);
    }

    layernorm_kernel<<<MROWS, 256>>>(p_resid, lnf_w, lnf_b, p_x);

    gemm_w<128,false,false><<<dim3(NVPAD/128, 16), 256, SMB128>>>(
        p_x, p_bu, b_U, nullptr, out, DMODEL, NVOCAB);
}

// round 8
// speedup vs baseline: 1.0297x; 1.0297x over previous
#include <cuda_runtime.h>
#include <mma.h>
#include <math.h>

using namespace nvcuda;

#define LYRS 12
#define NH 12
#define DMODEL 768
#define DHEAD 64
#define DMLP 3072
#define NVOCAB 50257
#define NVPAD 50304
#define BATCH 2
#define SEQ 1024
#define MROWS 2048

// ---- scratch (device globals; no allocation allowed) ----
__device__ float g_resid[MROWS*DMODEL];
__device__ float g_x[MROWS*DMODEL];
__device__ float g_q[MROWS*DMODEL];
__device__ float g_k[MROWS*DMODEL];
__device__ float g_v[MROWS*DMODEL];
__device__ float g_z[MROWS*DMODEL];
__device__ float g_h[MROWS*DMLP];
// repacked K-major [N][K] tf32-rounded weights
__device__ float g_bq[LYRS*DMODEL*DMODEL];
__device__ float g_bk[LYRS*DMODEL*DMODEL];
__device__ float g_bv[LYRS*DMODEL*DMODEL];
__device__ float g_bo[LYRS*DMODEL*DMODEL];
__device__ float g_bin[LYRS*DMLP*DMODEL];
__device__ float g_bout[LYRS*DMODEL*DMLP];
__device__ float g_bu[(long)NVPAD*DMODEL];

__device__ __forceinline__ float to_tf32(float x) {
    unsigned u; asm("cvt.rna.tf32.f32 %0, %1;" : "=r"(u) : "f"(x));
    return __uint_as_float(u);
}
__device__ __forceinline__ void cpa16(float* dst, const float* src) {
    unsigned d = (unsigned)__cvta_generic_to_shared(dst);
    asm volatile("cp.async.cg.shared.global [%0], [%1], 16;" :: "r"(d), "l"(src));
}

// ---- embedding ----
__global__ void embed_kernel(const int* __restrict__ tokens, const float* __restrict__ WE,
                             const float* __restrict__ Wpos, float* __restrict__ resid)
{
    int idx = blockIdx.x * blockDim.x + threadIdx.x;
    if (idx >= MROWS*DMODEL) return;
    int d = idx % DMODEL, bs = idx / DMODEL, s = bs % SEQ;
    resid[idx] = WE[(long)tokens[bs]*DMODEL + d] + Wpos[s*DMODEL + d];
}

// ---- layernorm (rounds output to tf32) ----
__global__ void layernorm_kernel(const float* __restrict__ in, const float* __restrict__ w,
                                 const float* __restrict__ b, float* __restrict__ out)
{
    __shared__ float sm[16];
    int row = blockIdx.x, tid = threadIdx.x;
    const float* x = in + (long)row * DMODEL;
    float s = 0.f, ss = 0.f;
    for (int i = tid; i < DMODEL; i += 256) { float v = x[i]; s += v; ss += v*v; }
    #pragma unroll
    for (int o = 16; o > 0; o >>= 1) {
        s  += __shfl_xor_sync(0xffffffffu, s,  o);
        ss += __shfl_xor_sync(0xffffffffu, ss, o);
    }
    if ((tid & 31) == 0) { sm[tid>>5] = s; sm[8 + (tid>>5)] = ss; }
    __syncthreads();
    if (tid < 8) {
        float a = sm[tid], c = sm[8+tid];
        #pragma unroll
        for (int o = 4; o > 0; o >>= 1) {
            a += __shfl_xor_sync(0xffu, a, o);
            c += __shfl_xor_sync(0xffu, c, o);
        }
        if (tid == 0) { sm[0] = a; sm[8] = c; }
    }
    __syncthreads();
    float mean = sm[0] * (1.f/DMODEL);
    float var  = sm[8] * (1.f/DMODEL) - mean*mean;
    float inv  = rsqrtf(var + 1e-5f);
    for (int i = tid; i < DMODEL; i += 256)
        out[(long)row*DMODEL + i] = to_tf32((x[i]-mean)*inv*w[i] + b[i]);
}

// ---- weight repack: per-head [L][H][D][DH] -> [L][h*64+e][D] (tf32) ----
__global__ void trans_head(const float* __restrict__ src, float* __restrict__ dst)
{
    __shared__ float t[32][33];
    int tx = threadIdx.x, ty = threadIdx.y;
    int d0 = blockIdx.x*32, e0 = blockIdx.y*32, lh = blockIdx.z;
    int l = lh / NH, h = lh % NH;
    const float* sp = src + (long)lh*DMODEL*DHEAD;
    float* dp = dst + (long)l*DMODEL*DMODEL;
    #pragma unroll
    for (int i = 0; i < 4; i++)
        t[ty+8*i][tx] = sp[(long)(d0+ty+8*i)*DHEAD + e0+tx];
    __syncthreads();
    #pragma unroll
    for (int i = 0; i < 4; i++)
        dp[(long)(h*64 + e0+ty+8*i)*DMODEL + d0+tx] = to_tf32(t[tx][ty+8*i]);
}

// ---- weight repack: [K,N] -> [Npad,K] transpose (tf32, zero pad) ----
__global__ void trans_kn(const float* __restrict__ src, float* __restrict__ dst,
                         int K, int N, int Npad)
{
    __shared__ float t[32][33];
    int tx = threadIdx.x, ty = threadIdx.y;
    int n0 = blockIdx.x*32, k0 = blockIdx.y*32, l = blockIdx.z;
    const float* sp = src + (long)l*K*N;
    float* dp = dst + (long)l*Npad*K;
    #pragma unroll
    for (int i = 0; i < 4; i++) {
        int n = n0+tx;
        t[ty+8*i][tx] = (n < N) ? sp[(long)(k0+ty+8*i)*N + n] : 0.f;
    }
    __syncthreads();
    #pragma unroll
    for (int i = 0; i < 4; i++)
        dp[(long)(n0+ty+8*i)*K + k0+tx] = to_tf32(t[tx][ty+8*i]);
}

// ---- wmma tf32 GEMM: C[2048,nvalid] = A[2048,K] @ B[Npad,K]^T ----
// TM x 128 block tile, BK=16, 4-stage cp.async, 8 warps.
// Grid: blockIdx.x = m-tile (fast), blockIdx.y = n-tile — so CTAs sharing a
// B tile are co-resident and B is served from L2 once.
#define ALD 20
#define CLD 132

typedef wmma::fragment<wmma::matrix_a, 16,16,8, wmma::precision::tf32, wmma::row_major> AFrag;
typedef wmma::fragment<wmma::matrix_b, 16,16,8, wmma::precision::tf32, wmma::col_major> BFrag;
typedef wmma::fragment<wmma::accumulator, 16,16,8, float> CFrag;

template<int TM, bool GELU, bool RES>
__device__ __forceinline__ void gemm_core(
    const float* __restrict__ A, const float* __restrict__ B,
    const float* __restrict__ bias, const float* __restrict__ res,
    float* __restrict__ C, int K, int nvalid)
{
    extern __shared__ float smem[];
    const int STAGE = (TM + 128)*ALD;
    const int MF = TM/32;
    int tid = threadIdx.x, wid = tid >> 5;
    int bm = blockIdx.x * TM, bn = blockIdx.y * 128;
    int wm = (wid >> 2) * (TM/2);
    int wn = (wid & 3) * 32;

    CFrag acc[TM/32][2];
    #pragma unroll
    for (int i = 0; i < MF; i++)
        #pragma unroll
        for (int j = 0; j < 2; j++) wmma::fill_fragment(acc[i][j], 0.f);

    auto loadStage = [&](int s, int it) {
        float* as = smem + s*STAGE;
        float* bs = as + TM*ALD;
        const float* Ag = A + (long)bm*K + it*16;
        const float* Bg = B + (long)bn*K + it*16;
        #pragma unroll
        for (int i = 0; i < TM/64; i++) {
            int idx = tid + 256*i;
            int row = idx >> 2, k4 = (idx & 3) << 2;
            cpa16(as + row*ALD + k4, Ag + (long)row*K + k4);
        }
        #pragma unroll
        for (int i = 0; i < 2; i++) {
            int idx = tid + 256*i;
            int row = idx >> 2, k4 = (idx & 3) << 2;
            cpa16(bs + row*ALD + k4, Bg + (long)row*K + k4);
        }
        asm volatile("cp.async.commit_group;" ::);
    };

    const int nIter = K >> 4;
    loadStage(0, 0);
    loadStage(1, 1);
    loadStage(2, 2);

    for (int it = 0; it < nIter; it++) {
        int cur = it & 3;
        if (it + 3 < nIter) asm volatile("cp.async.wait_group 2;" ::);
        else                asm volatile("cp.async.wait_group 0;" ::);
        __syncthreads();
        if (it + 3 < nIter) loadStage((it+3) & 3, it+3);

        const float* as = smem + cur*STAGE;
        const float* bs = as + TM*ALD;
        #pragma unroll
        for (int ks = 0; ks < 2; ks++) {
            AFrag af[TM/32];
            BFrag bf[2];
            #pragma unroll
            for (int mi = 0; mi < MF; mi++)
                wmma::load_matrix_sync(af[mi], as + (wm + mi*16)*ALD + ks*8, ALD);
            #pragma unroll
            for (int ni = 0; ni < 2; ni++)
                wmma::load_matrix_sync(bf[ni], bs + (wn + ni*16)*ALD + ks*8, ALD);
            #pragma unroll
            for (int mi = 0; mi < MF; mi++)
                #pragma unroll
                for (int ni = 0; ni < 2; ni++)
                    wmma::mma_sync(acc[mi][ni], af[mi], bf[ni], acc[mi][ni]);
        }
        __syncthreads();
    }

    // epilogue via smem (alias stages)
    float* Cs = smem;
    #pragma unroll
    for (int mi = 0; mi < MF; mi++)
        #pragma unroll
        for (int ni = 0; ni < 2; ni++)
            wmma::store_matrix_sync(Cs + (wm + mi*16)*CLD + wn + ni*16,
                                    acc[mi][ni], CLD, wmma::mem_row_major);
    __syncthreads();

    for (int idx = tid; idx < TM*128; idx += 256) {
        int r = idx >> 7, c = idx & 127;
        int n = bn + c;
        if (n < nvalid) {
            float v = Cs[r*CLD + c] + bias[n];
            long gr = bm + r;
            if (RES) v += res[gr*nvalid + n];
            if (GELU) {
                float t3 = v*v*v;
                v = 0.5f*v*(1.f + tanhf(0.7978845608028654f*(v + 0.044715f*t3)));
                v = to_tf32(v);
            }
            C[gr*nvalid + n] = v;
        }
    }
}

template<int TM, bool GELU, bool RES>
__global__ void __launch_bounds__(256) gemm_w(
    const float* __restrict__ A, const float* __restrict__ B,
    const float* __restrict__ bias, const float* __restrict__ res,
    float* __restrict__ C, int K, int nvalid)
{
    gemm_core<TM,GELU,RES>(A, B, bias, res, C, K, nvalid);
}

__global__ void __launch_bounds__(256) qkv_w(
    const float* __restrict__ A,
    const float* __restrict__ Bq, const float* __restrict__ Bk, const float* __restrict__ Bv,
    const float* __restrict__ bq, const float* __restrict__ bk, const float* __restrict__ bv,
    float* __restrict__ q, float* __restrict__ k, float* __restrict__ v)
{
    const float* B; const float* bias; float* C;
    int z = blockIdx.z;
    if (z == 0)      { B = Bq; bias = bq; C = q; }
    else if (z == 1) { B = Bk; bias = bk; C = k; }
    else             { B = Bv; bias = bv; C = v; }
    gemm_core<128,false,false>(A, B, bias, nullptr, C, DMODEL, DMODEL);
}

// ---- flash attention: block per (64 q-rows, h, b); 128 threads ----
__global__ void __launch_bounds__(128) flash_kernel(
    const float* __restrict__ q, const float* __restrict__ k,
    const float* __restrict__ v, float* __restrict__ z)
{
    __shared__ float Qs[64][68];
    __shared__ float Ks[32][68];
    __shared__ float Vs[32][68];
    __shared__ float Ss[64][33];
    int tid = threadIdx.x;
    int r = tid & 63, hf = tid >> 6;
    int qt = blockIdx.x, h = blockIdx.y, b = blockIdx.z;
    int qi = qt*64 + r;

    #pragma unroll 8
    for (int i = 0; i < 32; i++) {
        int lin = tid + 128*i;
        int row = lin >> 6, col = lin & 63;
        Qs[row][col] = q[(long)(b*SEQ + qt*64 + row)*DMODEL + h*DHEAD + col];
    }

    float o[32];
    #pragma unroll
    for (int e = 0; e < 32; e++) o[e] = 0.f;
    float m = -1e30f, l = 0.f;

    int ntiles = qt*2 + 2;
    for (int kt = 0; kt < ntiles; kt++) {
        __syncthreads();
        long kb = (long)(b*SEQ + kt*32)*DMODEL + h*DHEAD;
        #pragma unroll 4
        for (int i = 0; i < 16; i++) {
            int lin = tid + 128*i;
            int row = lin >> 6, col = lin & 63;
            Ks[row][col] = k[kb + (long)row*DMODEL + col];
            Vs[row][col] = v[kb + (long)row*DMODEL + col];
        }
        __syncthreads();
        #pragma unroll
        for (int jg = 0; jg < 2; jg++) {
            float sa[8];
            #pragma unroll
            for (int i = 0; i < 8; i++) sa[i] = 0.f;
            #pragma unroll
            for (int e4 = 0; e4 < 16; e4++) {
                float4 qv = *(const float4*)&Qs[r][e4*4];
                #pragma unroll
                for (int i = 0; i < 8; i++) {
                    float4 kk = *(const float4*)&Ks[hf*16 + jg*8 + i][e4*4];
                    sa[i] += qv.x*kk.x + qv.y*kk.y + qv.z*kk.z + qv.w*kk.w;
                }
            }
            #pragma unroll
            for (int i = 0; i < 8; i++) Ss[r][hf*16 + jg*8 + i] = sa[i];
        }
        __syncthreads();
        float p[32];
        float tmax = -1e30f;
        #pragma unroll
        for (int j = 0; j < 32; j++) {
            int kj = kt*32 + j;
            float sv = (kj <= qi) ? Ss[r][j]*0.125f : -1e30f;
            p[j] = sv;
            tmax = fmaxf(tmax, sv);
        }
        float mn = fmaxf(m, tmax);
        float sc = __expf(m - mn);
        float ts = 0.f;
        #pragma unroll
        for (int j = 0; j < 32; j++) {
            float pj = __expf(p[j] - mn);
            p[j] = pj;
            ts += pj;
        }
        l = l*sc + ts;
        m = mn;
        #pragma unroll
        for (int e = 0; e < 32; e++) o[e] *= sc;
        for (int j = 0; j < 32; j++) {
            float pj = p[j];
            #pragma unroll
            for (int e4 = 0; e4 < 8; e4++) {
                float4 vv = *(const float4*)&Vs[j][hf*32 + e4*4];
                o[e4*4+0] += pj*vv.x; o[e4*4+1] += pj*vv.y;
                o[e4*4+2] += pj*vv.z; o[e4*4+3] += pj*vv.w;
            }
        }
    }
    float inv = 1.f / l;
    long zrow = (long)(b*SEQ + qi)*DMODEL + h*DHEAD + hf*32;
    #pragma unroll
    for (int e = 0; e < 32; e++) z[zrow + e] = to_tf32(o[e]*inv);
}

// smem bytes: 4 stages vs epilogue restage
#define SMB128 (4*(128+128)*ALD*4 > 128*CLD*4 ? 4*(128+128)*ALD*4 : 128*CLD*4)  // 81920
#define SMB64  (4*(64+128)*ALD*4 > 64*CLD*4 ? 4*(64+128)*ALD*4 : 64*CLD*4)      // 61440

extern "C" void kernel_launch(void* const* d_in, const int* in_sizes, int n_in,
                              void* d_out, int out_size)
{
    const int*   tokens = (const int*)  d_in[0];
    const float* W_E    = (const float*)d_in[1];
    const float* W_pos  = (const float*)d_in[2];
    const float* ln1_w  = (const float*)d_in[3];
    const float* ln1_b  = (const float*)d_in[4];
    const float* W_Q    = (const float*)d_in[5];
    const float* b_Q    = (const float*)d_in[6];
    const float* W_K    = (const float*)d_in[7];
    const float* b_K    = (const float*)d_in[8];
    const float* W_V    = (const float*)d_in[9];
    const float* b_V    = (const float*)d_in[10];
    const float* W_O    = (const float*)d_in[11];
    const float* b_O    = (const float*)d_in[12];
    const float* ln2_w  = (const float*)d_in[13];
    const float* ln2_b  = (const float*)d_in[14];
    const float* W_in   = (const float*)d_in[15];
    const float* b_in   = (const float*)d_in[16];
    const float* W_out  = (const float*)d_in[17];
    const float* b_out  = (const float*)d_in[18];
    const float* lnf_w  = (const float*)d_in[19];
    const float* lnf_b  = (const float*)d_in[20];
    const float* W_U    = (const float*)d_in[21];
    const float* b_U    = (const float*)d_in[22];
    float* out = (float*)d_out;

    float *p_resid, *p_x, *p_q, *p_k, *p_v, *p_z, *p_h;
    float *p_bq, *p_bk, *p_bv, *p_bo, *p_bin, *p_bout, *p_bu;
    cudaGetSymbolAddress((void**)&p_resid, g_resid);
    cudaGetSymbolAddress((void**)&p_x, g_x);
    cudaGetSymbolAddress((void**)&p_q, g_q);
    cudaGetSymbolAddress((void**)&p_k, g_k);
    cudaGetSymbolAddress((void**)&p_v, g_v);
    cudaGetSymbolAddress((void**)&p_z, g_z);
    cudaGetSymbolAddress((void**)&p_h, g_h);
    cudaGetSymbolAddress((void**)&p_bq, g_bq);
    cudaGetSymbolAddress((void**)&p_bk, g_bk);
    cudaGetSymbolAddress((void**)&p_bv, g_bv);
    cudaGetSymbolAddress((void**)&p_bo, g_bo);
    cudaGetSymbolAddress((void**)&p_bin, g_bin);
    cudaGetSymbolAddress((void**)&p_bout, g_bout);
    cudaGetSymbolAddress((void**)&p_bu, g_bu);

    cudaFuncSetAttribute((const void*)gemm_w<128,false,false>, cudaFuncAttributeMaxDynamicSharedMemorySize, SMB128);
    cudaFuncSetAttribute((const void*)gemm_w<128,true,false>,  cudaFuncAttributeMaxDynamicSharedMemorySize, SMB128);
    cudaFuncSetAttribute((const void*)gemm_w<64,false,true>,   cudaFuncAttributeMaxDynamicSharedMemorySize, SMB64);
    cudaFuncSetAttribute((const void*)qkv_w,                   cudaFuncAttributeMaxDynamicSharedMemorySize, SMB128);

    dim3 tb(32, 8);
    trans_head<<<dim3(24, 2, LYRS*NH), tb>>>(W_Q, p_bq);
    trans_head<<<dim3(24, 2, LYRS*NH), tb>>>(W_K, p_bk);
    trans_head<<<dim3(24, 2, LYRS*NH), tb>>>(W_V, p_bv);
    trans_kn<<<dim3(24, 24, LYRS), tb>>>(W_O, p_bo, DMODEL, DMODEL, DMODEL);
    trans_kn<<<dim3(96, 24, LYRS), tb>>>(W_in, p_bin, DMODEL, DMLP, DMLP);
    trans_kn<<<dim3(24, 96, LYRS), tb>>>(W_out, p_bout, DMLP, DMODEL, DMODEL);
    trans_kn<<<dim3(NVPAD/32, 24, 1), tb>>>(W_U, p_bu, DMODEL, NVOCAB, NVPAD);

    embed_kernel<<<(MROWS*DMODEL + 255)/256, 256>>>(tokens, W_E, W_pos, p_resid);

    for (int l = 0; l < LYRS; l++) {
        layernorm_kernel<<<MROWS, 256>>>(p_resid, ln1_w + l*DMODEL, ln1_b + l*DMODEL, p_x);

        // grid: x = m-tiles (fast), y = n-tiles, z = q/k/v
        qkv_w<<<dim3(16, 6, 3), 256, SMB128>>>(
            p_x,
            p_bq + (long)l*DMODEL*DMODEL, p_bk + (long)l*DMODEL*DMODEL, p_bv + (long)l*DMODEL*DMODEL,
            b_Q + l*DMODEL, b_K + l*DMODEL, b_V + l*DMODEL,
            p_q, p_k, p_v);

        flash_kernel<<<dim3(SEQ/64, NH, BATCH), 128>>>(p_q, p_k, p_v, p_z);

        gemm_w<64,false,true><<<dim3(32, 6), 256, SMB64>>>(
            p_z, p_bo + (long)l*DMODEL*DMODEL, b_O + l*DMODEL, p_resid, p_resid,
            DMODEL, DMODEL);

        layernorm_kernel<<<MROWS, 256>>>(p_resid, ln2_w + l*DMODEL, ln2_b + l*DMODEL, p_x);

        gemm_w<128,true,false><<<dim3(16, 24), 256, SMB128>>>(
            p_x, p_bin + (long)l*DMLP*DMODEL, b_in + l*DMLP, nullptr, p_h,
            DMODEL, DMLP);

        gemm_w<64,false,true><<<dim3(32, 6), 256, SMB64>>>(
            p_h, p_bout + (long)l*DMODEL*DMLP, b_out + l*DMODEL, p_resid, p_resid,
            DMLP, DMODEL);
    }

    layernorm_kernel<<<MROWS, 256>>>(p_resid, lnf_w, lnf_b, p_x);

    gemm_w<128,false,false><<<dim3(16, NVPAD/128), 256, SMB128>>>(
        p_x, p_bu, b_U, nullptr, out, DMODEL, NVOCAB);
}

// round 9
// speedup vs baseline: 1.0522x; 1.0218x over previous
#include <cuda_runtime.h>
#include <mma.h>
#include <math.h>

using namespace nvcuda;

#define LYRS 12
#define NH 12
#define DMODEL 768
#define DHEAD 64
#define DMLP 3072
#define NVOCAB 50257
#define NVPAD 50304
#define BATCH 2
#define SEQ 1024
#define MROWS 2048

// ---- scratch (device globals; no allocation allowed) ----
__device__ float g_resid[MROWS*DMODEL];
__device__ float g_x[MROWS*DMODEL];
__device__ float g_q[MROWS*DMODEL];
__device__ float g_k[MROWS*DMODEL];
__device__ float g_v[MROWS*DMODEL];
__device__ float g_z[MROWS*DMODEL];
__device__ float g_h[MROWS*DMLP];
// repacked K-major [N][K] tf32-rounded weights
__device__ float g_bq[LYRS*DMODEL*DMODEL];
__device__ float g_bk[LYRS*DMODEL*DMODEL];
__device__ float g_bv[LYRS*DMODEL*DMODEL];
__device__ float g_bo[LYRS*DMODEL*DMODEL];
__device__ float g_bin[LYRS*DMLP*DMODEL];
__device__ float g_bout[LYRS*DMODEL*DMLP];
__device__ float g_bu[(long)NVPAD*DMODEL];

__device__ __forceinline__ float to_tf32(float x) {
    unsigned u; asm("cvt.rna.tf32.f32 %0, %1;" : "=r"(u) : "f"(x));
    return __uint_as_float(u);
}
__device__ __forceinline__ void cpa16(float* dst, const float* src) {
    unsigned d = (unsigned)__cvta_generic_to_shared(dst);
    asm volatile("cp.async.cg.shared.global [%0], [%1], 16;" :: "r"(d), "l"(src));
}

// ---- embedding ----
__global__ void embed_kernel(const int* __restrict__ tokens, const float* __restrict__ WE,
                             const float* __restrict__ Wpos, float* __restrict__ resid)
{
    int idx = blockIdx.x * blockDim.x + threadIdx.x;
    if (idx >= MROWS*DMODEL) return;
    int d = idx % DMODEL, bs = idx / DMODEL, s = bs % SEQ;
    resid[idx] = WE[(long)tokens[bs]*DMODEL + d] + Wpos[s*DMODEL + d];
}

// ---- layernorm (rounds output to tf32) ----
__global__ void layernorm_kernel(const float* __restrict__ in, const float* __restrict__ w,
                                 const float* __restrict__ b, float* __restrict__ out)
{
    __shared__ float sm[16];
    int row = blockIdx.x, tid = threadIdx.x;
    const float* x = in + (long)row * DMODEL;
    float s = 0.f, ss = 0.f;
    for (int i = tid; i < DMODEL; i += 256) { float v = x[i]; s += v; ss += v*v; }
    #pragma unroll
    for (int o = 16; o > 0; o >>= 1) {
        s  += __shfl_xor_sync(0xffffffffu, s,  o);
        ss += __shfl_xor_sync(0xffffffffu, ss, o);
    }
    if ((tid & 31) == 0) { sm[tid>>5] = s; sm[8 + (tid>>5)] = ss; }
    __syncthreads();
    if (tid < 8) {
        float a = sm[tid], c = sm[8+tid];
        #pragma unroll
        for (int o = 4; o > 0; o >>= 1) {
            a += __shfl_xor_sync(0xffu, a, o);
            c += __shfl_xor_sync(0xffu, c, o);
        }
        if (tid == 0) { sm[0] = a; sm[8] = c; }
    }
    __syncthreads();
    float mean = sm[0] * (1.f/DMODEL);
    float var  = sm[8] * (1.f/DMODEL) - mean*mean;
    float inv  = rsqrtf(var + 1e-5f);
    for (int i = tid; i < DMODEL; i += 256)
        out[(long)row*DMODEL + i] = to_tf32((x[i]-mean)*inv*w[i] + b[i]);
}

// ---- weight repack: per-head [L][H][D][DH] -> [L][h*64+e][D] (tf32) ----
__global__ void trans_head(const float* __restrict__ src, float* __restrict__ dst)
{
    __shared__ float t[32][33];
    int tx = threadIdx.x, ty = threadIdx.y;
    int d0 = blockIdx.x*32, e0 = blockIdx.y*32, lh = blockIdx.z;
    int l = lh / NH, h = lh % NH;
    const float* sp = src + (long)lh*DMODEL*DHEAD;
    float* dp = dst + (long)l*DMODEL*DMODEL;
    #pragma unroll
    for (int i = 0; i < 4; i++)
        t[ty+8*i][tx] = sp[(long)(d0+ty+8*i)*DHEAD + e0+tx];
    __syncthreads();
    #pragma unroll
    for (int i = 0; i < 4; i++)
        dp[(long)(h*64 + e0+ty+8*i)*DMODEL + d0+tx] = to_tf32(t[tx][ty+8*i]);
}

// ---- weight repack: [K,N] -> [Npad,K] transpose (tf32, zero pad) ----
__global__ void trans_kn(const float* __restrict__ src, float* __restrict__ dst,
                         int K, int N, int Npad)
{
    __shared__ float t[32][33];
    int tx = threadIdx.x, ty = threadIdx.y;
    int n0 = blockIdx.x*32, k0 = blockIdx.y*32, l = blockIdx.z;
    const float* sp = src + (long)l*K*N;
    float* dp = dst + (long)l*Npad*K;
    #pragma unroll
    for (int i = 0; i < 4; i++) {
        int n = n0+tx;
        t[ty+8*i][tx] = (n < N) ? sp[(long)(k0+ty+8*i)*N + n] : 0.f;
    }
    __syncthreads();
    #pragma unroll
    for (int i = 0; i < 4; i++)
        dp[(long)(n0+ty+8*i)*K + k0+tx] = to_tf32(t[tx][ty+8*i]);
}

// ---- wmma tf32 GEMM: C[2048,nvalid] = A[2048,K] @ B[Npad,K]^T ----
// TM x 128 block tile, BK=16, 3-stage cp.async, 8 warps. (champion config)
// MFAST: blockIdx.x indexes m (fast) so CTAs sharing a B tile co-reside (L2 reuse).
#define ALD 20
#define CLD 132

typedef wmma::fragment<wmma::matrix_a, 16,16,8, wmma::precision::tf32, wmma::row_major> AFrag;
typedef wmma::fragment<wmma::matrix_b, 16,16,8, wmma::precision::tf32, wmma::col_major> BFrag;
typedef wmma::fragment<wmma::accumulator, 16,16,8, float> CFrag;

template<int TM, bool GELU, bool RES, bool MFAST>
__device__ __forceinline__ void gemm_core(
    const float* __restrict__ A, const float* __restrict__ B,
    const float* __restrict__ bias, const float* __restrict__ res,
    float* __restrict__ C, int K, int nvalid)
{
    extern __shared__ float smem[];
    const int STAGE = (TM + 128)*ALD;
    const int MF = TM/32;
    int tid = threadIdx.x, wid = tid >> 5;
    int bm = (MFAST ? blockIdx.x : blockIdx.y) * TM;
    int bn = (MFAST ? blockIdx.y : blockIdx.x) * 128;
    int wm = (wid >> 2) * (TM/2);
    int wn = (wid & 3) * 32;

    CFrag acc[TM/32][2];
    #pragma unroll
    for (int i = 0; i < MF; i++)
        #pragma unroll
        for (int j = 0; j < 2; j++) wmma::fill_fragment(acc[i][j], 0.f);

    auto loadStage = [&](int s, int it) {
        float* as = smem + s*STAGE;
        float* bs = as + TM*ALD;
        const float* Ag = A + (long)bm*K + it*16;
        const float* Bg = B + (long)bn*K + it*16;
        #pragma unroll
        for (int i = 0; i < TM/64; i++) {
            int idx = tid + 256*i;
            int row = idx >> 2, k4 = (idx & 3) << 2;
            cpa16(as + row*ALD + k4, Ag + (long)row*K + k4);
        }
        #pragma unroll
        for (int i = 0; i < 2; i++) {
            int idx = tid + 256*i;
            int row = idx >> 2, k4 = (idx & 3) << 2;
            cpa16(bs + row*ALD + k4, Bg + (long)row*K + k4);
        }
        asm volatile("cp.async.commit_group;" ::);
    };

    const int nIter = K >> 4;
    loadStage(0, 0);
    if (nIter > 1) loadStage(1, 1); else asm volatile("cp.async.commit_group;" ::);

    for (int it = 0; it < nIter; it++) {
        int cur = it % 3;
        if (it + 2 < nIter) asm volatile("cp.async.wait_group 1;" ::);
        else                asm volatile("cp.async.wait_group 0;" ::);
        __syncthreads();
        if (it + 2 < nIter) loadStage((it+2) % 3, it+2);

        const float* as = smem + cur*STAGE;
        const float* bs = as + TM*ALD;
        #pragma unroll
        for (int ks = 0; ks < 2; ks++) {
            AFrag af[TM/32];
            BFrag bf[2];
            #pragma unroll
            for (int mi = 0; mi < MF; mi++)
                wmma::load_matrix_sync(af[mi], as + (wm + mi*16)*ALD + ks*8, ALD);
            #pragma unroll
            for (int ni = 0; ni < 2; ni++)
                wmma::load_matrix_sync(bf[ni], bs + (wn + ni*16)*ALD + ks*8, ALD);
            #pragma unroll
            for (int mi = 0; mi < MF; mi++)
                #pragma unroll
                for (int ni = 0; ni < 2; ni++)
                    wmma::mma_sync(acc[mi][ni], af[mi], bf[ni], acc[mi][ni]);
        }
        __syncthreads();
    }

    // epilogue via smem (alias stages)
    float* Cs = smem;
    #pragma unroll
    for (int mi = 0; mi < MF; mi++)
        #pragma unroll
        for (int ni = 0; ni < 2; ni++)
            wmma::store_matrix_sync(Cs + (wm + mi*16)*CLD + wn + ni*16,
                                    acc[mi][ni], CLD, wmma::mem_row_major);
    __syncthreads();

    for (int idx = tid; idx < TM*128; idx += 256) {
        int r = idx >> 7, c = idx & 127;
        int n = bn + c;
        if (n < nvalid) {
            float v = Cs[r*CLD + c] + bias[n];
            long gr = bm + r;
            if (RES) v += res[gr*nvalid + n];
            if (GELU) {
                float t3 = v*v*v;
                v = 0.5f*v*(1.f + tanhf(0.7978845608028654f*(v + 0.044715f*t3)));
                v = to_tf32(v);
            }
            C[gr*nvalid + n] = v;
        }
    }
}

template<int TM, bool GELU, bool RES, bool MFAST>
__global__ void __launch_bounds__(256) gemm_w(
    const float* __restrict__ A, const float* __restrict__ B,
    const float* __restrict__ bias, const float* __restrict__ res,
    float* __restrict__ C, int K, int nvalid)
{
    gemm_core<TM,GELU,RES,MFAST>(A, B, bias, res, C, K, nvalid);
}

__global__ void __launch_bounds__(256) qkv_w(
    const float* __restrict__ A,
    const float* __restrict__ Bq, const float* __restrict__ Bk, const float* __restrict__ Bv,
    const float* __restrict__ bq, const float* __restrict__ bk, const float* __restrict__ bv,
    float* __restrict__ q, float* __restrict__ k, float* __restrict__ v)
{
    const float* B; const float* bias; float* C;
    int z = blockIdx.z;
    if (z == 0)      { B = Bq; bias = bq; C = q; }
    else if (z == 1) { B = Bk; bias = bk; C = k; }
    else             { B = Bv; bias = bv; C = v; }
    gemm_core<128,false,false,false>(A, B, bias, nullptr, C, DMODEL, DMODEL);
}

// ---- flash attention: block per (64 q-rows, h, b); 64 threads, 1 row/thread ----
__global__ void __launch_bounds__(64) flash_kernel(
    const float* __restrict__ q, const float* __restrict__ k,
    const float* __restrict__ v, float* __restrict__ z)
{
    __shared__ float Qs[64][68];
    __shared__ float Ks[32][68];
    __shared__ float Vs[32][68];
    __shared__ float Ss[64][33];
    int tid = threadIdx.x;
    int qt = blockIdx.x, h = blockIdx.y, b = blockIdx.z;
    int qi = qt*64 + tid;
    long qrow = (long)(b*SEQ + qi)*DMODEL + h*DHEAD;

    for (int r = 0; r < 64; r++)
        Qs[r][tid] = q[(long)(b*SEQ + qt*64 + r)*DMODEL + h*DHEAD + tid];

    float o[64];
    #pragma unroll
    for (int e = 0; e < 64; e++) o[e] = 0.f;
    float m = -1e30f, l = 0.f;

    int ntiles = qt*2 + 2;
    for (int kt = 0; kt < ntiles; kt++) {
        __syncthreads();
        long kb = (long)(b*SEQ + kt*32)*DMODEL + h*DHEAD;
        for (int r = 0; r < 32; r++) {
            Ks[r][tid] = k[kb + (long)r*DMODEL + tid];
            Vs[r][tid] = v[kb + (long)r*DMODEL + tid];
        }
        __syncthreads();
        for (int jg = 0; jg < 4; jg++) {
            float sa[8];
            #pragma unroll
            for (int i = 0; i < 8; i++) sa[i] = 0.f;
            for (int e4 = 0; e4 < 16; e4++) {
                float4 qv = *(const float4*)&Qs[tid][e4*4];
                #pragma unroll
                for (int i = 0; i < 8; i++) {
                    float4 kk = *(const float4*)&Ks[jg*8 + i][e4*4];
                    sa[i] += qv.x*kk.x + qv.y*kk.y + qv.z*kk.z + qv.w*kk.w;
                }
            }
            #pragma unroll
            for (int i = 0; i < 8; i++) Ss[tid][jg*8 + i] = sa[i];
        }
        float tmax = -1e30f;
        for (int j = 0; j < 32; j++) {
            int kj = kt*32 + j;
            float sv = (kj <= qi) ? Ss[tid][j]*0.125f : -1e30f;
            Ss[tid][j] = sv;
            tmax = fmaxf(tmax, sv);
        }
        float mn = fmaxf(m, tmax);
        float sc = __expf(m - mn);
        float ts = 0.f;
        for (int j = 0; j < 32; j++) {
            float p = __expf(Ss[tid][j] - mn);
            Ss[tid][j] = p;
            ts += p;
        }
        l = l*sc + ts;
        m = mn;
        #pragma unroll
        for (int e = 0; e < 64; e++) o[e] *= sc;
        for (int j = 0; j < 32; j++) {
            float p = Ss[tid][j];
            #pragma unroll
            for (int e4 = 0; e4 < 16; e4++) {
                float4 vv = *(const float4*)&Vs[j][e4*4];
                o[e4*4+0] += p*vv.x; o[e4*4+1] += p*vv.y;
                o[e4*4+2] += p*vv.z; o[e4*4+3] += p*vv.w;
            }
        }
    }
    float inv = 1.f / l;
    #pragma unroll
    for (int e = 0; e < 64; e++) z[qrow + e] = to_tf32(o[e]*inv);
}

// smem sizes (bytes) — champion values
#define SMB128 (128*CLD*4)                 // 67584 (>= 3*STAGE128 = 61440)
#define SMB64  (3*(64+128)*ALD*4)          // 46080 (>= 64*CLD*4 = 33792)

extern "C" void kernel_launch(void* const* d_in, const int* in_sizes, int n_in,
                              void* d_out, int out_size)
{
    const int*   tokens = (const int*)  d_in[0];
    const float* W_E    = (const float*)d_in[1];
    const float* W_pos  = (const float*)d_in[2];
    const float* ln1_w  = (const float*)d_in[3];
    const float* ln1_b  = (const float*)d_in[4];
    const float* W_Q    = (const float*)d_in[5];
    const float* b_Q    = (const float*)d_in[6];
    const float* W_K    = (const float*)d_in[7];
    const float* b_K    = (const float*)d_in[8];
    const float* W_V    = (const float*)d_in[9];
    const float* b_V    = (const float*)d_in[10];
    const float* W_O    = (const float*)d_in[11];
    const float* b_O    = (const float*)d_in[12];
    const float* ln2_w  = (const float*)d_in[13];
    const float* ln2_b  = (const float*)d_in[14];
    const float* W_in   = (const float*)d_in[15];
    const float* b_in   = (const float*)d_in[16];
    const float* W_out  = (const float*)d_in[17];
    const float* b_out  = (const float*)d_in[18];
    const float* lnf_w  = (const float*)d_in[19];
    const float* lnf_b  = (const float*)d_in[20];
    const float* W_U    = (const float*)d_in[21];
    const float* b_U    = (const float*)d_in[22];
    float* out = (float*)d_out;

    float *p_resid, *p_x, *p_q, *p_k, *p_v, *p_z, *p_h;
    float *p_bq, *p_bk, *p_bv, *p_bo, *p_bin, *p_bout, *p_bu;
    cudaGetSymbolAddress((void**)&p_resid, g_resid);
    cudaGetSymbolAddress((void**)&p_x, g_x);
    cudaGetSymbolAddress((void**)&p_q, g_q);
    cudaGetSymbolAddress((void**)&p_k, g_k);
    cudaGetSymbolAddress((void**)&p_v, g_v);
    cudaGetSymbolAddress((void**)&p_z, g_z);
    cudaGetSymbolAddress((void**)&p_h, g_h);
    cudaGetSymbolAddress((void**)&p_bq, g_bq);
    cudaGetSymbolAddress((void**)&p_bk, g_bk);
    cudaGetSymbolAddress((void**)&p_bv, g_bv);
    cudaGetSymbolAddress((void**)&p_bo, g_bo);
    cudaGetSymbolAddress((void**)&p_bin, g_bin);
    cudaGetSymbolAddress((void**)&p_bout, g_bout);
    cudaGetSymbolAddress((void**)&p_bu, g_bu);

    cudaFuncSetAttribute((const void*)gemm_w<128,false,false,false>, cudaFuncAttributeMaxDynamicSharedMemorySize, SMB128);
    cudaFuncSetAttribute((const void*)gemm_w<128,false,false,true>,  cudaFuncAttributeMaxDynamicSharedMemorySize, SMB128);
    cudaFuncSetAttribute((const void*)gemm_w<128,true,false,false>,  cudaFuncAttributeMaxDynamicSharedMemorySize, SMB128);
    cudaFuncSetAttribute((const void*)gemm_w<64,false,true,false>,   cudaFuncAttributeMaxDynamicSharedMemorySize, SMB64);
    cudaFuncSetAttribute((const void*)qkv_w,                         cudaFuncAttributeMaxDynamicSharedMemorySize, SMB128);

    dim3 tb(32, 8);
    trans_head<<<dim3(24, 2, LYRS*NH), tb>>>(W_Q, p_bq);
    trans_head<<<dim3(24, 2, LYRS*NH), tb>>>(W_K, p_bk);
    trans_head<<<dim3(24, 2, LYRS*NH), tb>>>(W_V, p_bv);
    trans_kn<<<dim3(24, 24, LYRS), tb>>>(W_O, p_bo, DMODEL, DMODEL, DMODEL);
    trans_kn<<<dim3(96, 24, LYRS), tb>>>(W_in, p_bin, DMODEL, DMLP, DMLP);
    trans_kn<<<dim3(24, 96, LYRS), tb>>>(W_out, p_bout, DMLP, DMODEL, DMODEL);
    trans_kn<<<dim3(NVPAD/32, 24, 1), tb>>>(W_U, p_bu, DMODEL, NVOCAB, NVPAD);

    embed_kernel<<<(MROWS*DMODEL + 255)/256, 256>>>(tokens, W_E, W_pos, p_resid);

    for (int l = 0; l < LYRS; l++) {
        layernorm_kernel<<<MROWS, 256>>>(p_resid, ln1_w + l*DMODEL, ln1_b + l*DMODEL, p_x);

        qkv_w<<<dim3(6, 16, 3), 256, SMB128>>>(
            p_x,
            p_bq + (long)l*DMODEL*DMODEL, p_bk + (long)l*DMODEL*DMODEL, p_bv + (long)l*DMODEL*DMODEL,
            b_Q + l*DMODEL, b_K + l*DMODEL, b_V + l*DMODEL,
            p_q, p_k, p_v);

        flash_kernel<<<dim3(SEQ/64, NH, BATCH), 64>>>(p_q, p_k, p_v, p_z);

        gemm_w<64,false,true,false><<<dim3(6, 32), 256, SMB64>>>(
            p_z, p_bo + (long)l*DMODEL*DMODEL, b_O + l*DMODEL, p_resid, p_resid,
            DMODEL, DMODEL);

        layernorm_kernel<<<MROWS, 256>>>(p_resid, ln2_w + l*DMODEL, ln2_b + l*DMODEL, p_x);

        gemm_w<128,true,false,false><<<dim3(24, 16), 256, SMB128>>>(
            p_x, p_bin + (long)l*DMLP*DMODEL, b_in + l*DMLP, nullptr, p_h,
            DMODEL, DMLP);

        gemm_w<64,false,true,false><<<dim3(6, 32), 256, SMB64>>>(
            p_h, p_bout + (long)l*DMODEL*DMLP, b_out + l*DMODEL, p_resid, p_resid,
            DMLP, DMODEL);
    }

    layernorm_kernel<<<MROWS, 256>>>(p_resid, lnf_w, lnf_b, p_x);

    // m-fast grid: 16 m-tiles co-resident per B tile -> W_U read ~once from DRAM
    gemm_w<128,false,false,true><<<dim3(16, NVPAD/128), 256, SMB128>>>(
        p_x, p_bu, b_U, nullptr, out, DMODEL, NVOCAB);
}

// round 10
// speedup vs baseline: 1.5767x; 1.4984x over previous
#include <cuda_runtime.h>
#include <math.h>

#define LYRS 12
#define NH 12
#define DMODEL 768
#define DHEAD 64
#define DMLP 3072
#define NVOCAB 50257
#define NVPAD 50304
#define BATCH 2
#define SEQ 1024
#define MROWS 2048

// ---- scratch (device globals; no allocation allowed) ----
__device__ float g_resid[MROWS*DMODEL];
__device__ float g_x[MROWS*DMODEL];
__device__ float g_q[MROWS*DMODEL];
__device__ float g_k[MROWS*DMODEL];
__device__ float g_v[MROWS*DMODEL];
__device__ float g_z[MROWS*DMODEL];
__device__ float g_h[MROWS*DMLP];
// repacked K-major [N][K] tf32-rounded, k-interleaved weights
__device__ float g_bq[LYRS*DMODEL*DMODEL];
__device__ float g_bk[LYRS*DMODEL*DMODEL];
__device__ float g_bv[LYRS*DMODEL*DMODEL];
__device__ float g_bo[LYRS*DMODEL*DMODEL];
__device__ float g_bin[LYRS*DMLP*DMODEL];
__device__ float g_bout[LYRS*DMODEL*DMLP];
__device__ float g_bu[(long)NVPAD*DMODEL];

__device__ __forceinline__ float to_tf32(float x) {
    unsigned u; asm("cvt.rna.tf32.f32 %0, %1;" : "=r"(u) : "f"(x));
    return __uint_as_float(u);
}
// k-interleave: logical col c -> physical position within its 8-group.
// cols (t, t+4) land at (2t, 2t+1) so mma fragment pairs are contiguous.
__device__ __forceinline__ int kperm(int c) {
    return (c & ~7) | (((c & 3) << 1) | ((c >> 2) & 1));
}
__device__ __forceinline__ void cpa16(float* dst, const float* src) {
    unsigned d = (unsigned)__cvta_generic_to_shared(dst);
    asm volatile("cp.async.cg.shared.global [%0], [%1], 16;" :: "r"(d), "l"(src));
}

// ---- embedding ----
__global__ void embed_kernel(const int* __restrict__ tokens, const float* __restrict__ WE,
                             const float* __restrict__ Wpos, float* __restrict__ resid)
{
    int idx = blockIdx.x * blockDim.x + threadIdx.x;
    if (idx >= MROWS*DMODEL) return;
    int d = idx % DMODEL, bs = idx / DMODEL, s = bs % SEQ;
    resid[idx] = WE[(long)tokens[bs]*DMODEL + d] + Wpos[s*DMODEL + d];
}

// ---- layernorm: natural input, k-interleaved tf32 output ----
__global__ void layernorm_kernel(const float* __restrict__ in, const float* __restrict__ w,
                                 const float* __restrict__ b, float* __restrict__ out)
{
    __shared__ float sm[16];
    int row = blockIdx.x, tid = threadIdx.x;
    const float* x = in + (long)row * DMODEL;
    float s = 0.f, ss = 0.f;
    for (int i = tid; i < DMODEL; i += 256) { float v = x[i]; s += v; ss += v*v; }
    #pragma unroll
    for (int o = 16; o > 0; o >>= 1) {
        s  += __shfl_xor_sync(0xffffffffu, s,  o);
        ss += __shfl_xor_sync(0xffffffffu, ss, o);
    }
    if ((tid & 31) == 0) { sm[tid>>5] = s; sm[8 + (tid>>5)] = ss; }
    __syncthreads();
    if (tid < 8) {
        float a = sm[tid], c = sm[8+tid];
        #pragma unroll
        for (int o = 4; o > 0; o >>= 1) {
            a += __shfl_xor_sync(0xffu, a, o);
            c += __shfl_xor_sync(0xffu, c, o);
        }
        if (tid == 0) { sm[0] = a; sm[8] = c; }
    }
    __syncthreads();
    float mean = sm[0] * (1.f/DMODEL);
    float var  = sm[8] * (1.f/DMODEL) - mean*mean;
    float inv  = rsqrtf(var + 1e-5f);
    for (int i = tid; i < DMODEL; i += 256)
        out[(long)row*DMODEL + kperm(i)] = to_tf32((x[i]-mean)*inv*w[i] + b[i]);
}

// ---- weight repack: per-head [L][H][D][DH] -> [L][h*64+e][perm(D)] (tf32) ----
__global__ void trans_head(const float* __restrict__ src, float* __restrict__ dst)
{
    __shared__ float t[32][33];
    int tx = threadIdx.x, ty = threadIdx.y;
    int d0 = blockIdx.x*32, e0 = blockIdx.y*32, lh = blockIdx.z;
    int l = lh / NH, h = lh % NH;
    const float* sp = src + (long)lh*DMODEL*DHEAD;
    float* dp = dst + (long)l*DMODEL*DMODEL;
    #pragma unroll
    for (int i = 0; i < 4; i++)
        t[ty+8*i][tx] = sp[(long)(d0+ty+8*i)*DHEAD + e0+tx];
    __syncthreads();
    #pragma unroll
    for (int i = 0; i < 4; i++)
        dp[(long)(h*64 + e0+ty+8*i)*DMODEL + kperm(d0+tx)] = to_tf32(t[tx][ty+8*i]);
}

// ---- weight repack: [K,N] -> [Npad][perm(K)] transpose (tf32, zero pad) ----
__global__ void trans_kn(const float* __restrict__ src, float* __restrict__ dst,
                         int K, int N, int Npad)
{
    __shared__ float t[32][33];
    int tx = threadIdx.x, ty = threadIdx.y;
    int n0 = blockIdx.x*32, k0 = blockIdx.y*32, l = blockIdx.z;
    const float* sp = src + (long)l*K*N;
    float* dp = dst + (long)l*Npad*K;
    #pragma unroll
    for (int i = 0; i < 4; i++) {
        int n = n0+tx;
        t[ty+8*i][tx] = (n < N) ? sp[(long)(k0+ty+8*i)*N + n] : 0.f;
    }
    __syncthreads();
    #pragma unroll
    for (int i = 0; i < 4; i++)
        dp[(long)(n0+ty+8*i)*K + kperm(k0+tx)] = to_tf32(t[tx][ty+8*i]);
}

// ---- raw mma.sync tf32 GEMM: C[2048,nvalid] = A[2048,K] @ B[Npad,K]^T ----
// A and B stored k-interleaved. TM x 128 tile, BK=16, 3-stage cp.async, 8 warps.
// Warp tile (TM/2) x 32: MF m16-frags x 4 n8-frags, m16n8k8 mma.
#define KLD 24
#define CLD 132

template<int TM, bool GELU, bool RES, bool PERMC>
__device__ __forceinline__ void gemm_core(
    const float* __restrict__ A, const float* __restrict__ B,
    const float* __restrict__ bias, const float* __restrict__ res,
    float* __restrict__ C, int K, int nvalid)
{
    extern __shared__ float smem[];
    const int STAGE = (TM + 128)*KLD;
    const int MF = TM/32;
    int tid = threadIdx.x, wid = tid >> 5, lane = tid & 31;
    int gid = lane >> 2, tig = lane & 3;
    int bm = blockIdx.y * TM, bn = blockIdx.x * 128;
    int wm = (wid >> 2) * (TM/2);
    int wn = (wid & 3) * 32;

    float d[TM/32][4][4];
    #pragma unroll
    for (int mi = 0; mi < MF; mi++)
        #pragma unroll
        for (int ni = 0; ni < 4; ni++)
            #pragma unroll
            for (int r = 0; r < 4; r++) d[mi][ni][r] = 0.f;

    auto loadStage = [&](int s, int it) {
        float* as = smem + s*STAGE;
        float* bs = as + TM*KLD;
        const float* Ag = A + (long)bm*K + it*16;
        const float* Bg = B + (long)bn*K + it*16;
        #pragma unroll
        for (int i = 0; i < TM/64; i++) {
            int idx = tid + 256*i;
            int row = idx >> 2, k4 = (idx & 3) << 2;
            cpa16(as + row*KLD + k4, Ag + (long)row*K + k4);
        }
        #pragma unroll
        for (int i = 0; i < 2; i++) {
            int idx = tid + 256*i;
            int row = idx >> 2, k4 = (idx & 3) << 2;
            cpa16(bs + row*KLD + k4, Bg + (long)row*K + k4);
        }
        asm volatile("cp.async.commit_group;" ::);
    };

    const int nIter = K >> 4;
    loadStage(0, 0);
    loadStage(1, 1);

    for (int it = 0; it < nIter; it++) {
        int cur = it % 3;
        if (it + 2 < nIter) asm volatile("cp.async.wait_group 1;" ::);
        else                asm volatile("cp.async.wait_group 0;" ::);
        __syncthreads();
        if (it + 2 < nIter) loadStage((it+2) % 3, it+2);

        const float* as = smem + cur*STAGE;
        const float* bs = as + TM*KLD;
        #pragma unroll
        for (int kg = 0; kg < 2; kg++) {
            unsigned a[TM/32][4], b[4][2];
            #pragma unroll
            for (int mi = 0; mi < MF; mi++) {
                float2 v0 = *((const float2*)(as + (wm + mi*16 + gid)*KLD + kg*8) + tig);
                float2 v1 = *((const float2*)(as + (wm + mi*16 + gid + 8)*KLD + kg*8) + tig);
                a[mi][0] = __float_as_uint(v0.x); a[mi][2] = __float_as_uint(v0.y);
                a[mi][1] = __float_as_uint(v1.x); a[mi][3] = __float_as_uint(v1.y);
            }
            #pragma unroll
            for (int ni = 0; ni < 4; ni++) {
                float2 u = *((const float2*)(bs + (wn + ni*8 + gid)*KLD + kg*8) + tig);
                b[ni][0] = __float_as_uint(u.x); b[ni][1] = __float_as_uint(u.y);
            }
            #pragma unroll
            for (int mi = 0; mi < MF; mi++)
                #pragma unroll
                for (int ni = 0; ni < 4; ni++) {
                    float* dd = d[mi][ni];
                    asm volatile(
                        "mma.sync.aligned.m16n8k8.row.col.f32.tf32.tf32.f32 "
                        "{%0,%1,%2,%3}, {%4,%5,%6,%7}, {%8,%9}, {%0,%1,%2,%3};"
                        : "+f"(dd[0]), "+f"(dd[1]), "+f"(dd[2]), "+f"(dd[3])
                        : "r"(a[mi][0]), "r"(a[mi][1]), "r"(a[mi][2]), "r"(a[mi][3]),
                          "r"(b[ni][0]), "r"(b[ni][1]));
                }
        }
        __syncthreads();
    }

    // epilogue: stage through smem (alias stages), then guarded fused store
    float* Cs = smem;
    #pragma unroll
    for (int mi = 0; mi < MF; mi++)
        #pragma unroll
        for (int ni = 0; ni < 4; ni++) {
            float* dd = d[mi][ni];
            int col = wn + ni*8 + 2*tig;
            float* p0 = Cs + (wm + mi*16 + gid)*CLD + col;
            float* p1 = Cs + (wm + mi*16 + gid + 8)*CLD + col;
            p0[0] = dd[0]; p0[1] = dd[1];
            p1[0] = dd[2]; p1[1] = dd[3];
        }
    __syncthreads();

    for (int idx = tid; idx < TM*128; idx += 256) {
        int r = idx >> 7, c = idx & 127;
        int n = bn + c;
        if (n < nvalid) {
            float v = Cs[r*CLD + c] + bias[n];
            long gr = bm + r;
            if (RES) v += res[gr*nvalid + n];
            if (GELU) {
                float t3 = v*v*v;
                v = 0.5f*v*(1.f + tanhf(0.7978845608028654f*(v + 0.044715f*t3)));
                v = to_tf32(v);
            }
            C[gr*nvalid + (PERMC ? kperm(n) : n)] = v;
        }
    }
}

template<int TM, bool GELU, bool RES, bool PERMC>
__global__ void __launch_bounds__(256) gemm_w(
    const float* __restrict__ A, const float* __restrict__ B,
    const float* __restrict__ bias, const float* __restrict__ res,
    float* __restrict__ C, int K, int nvalid)
{
    gemm_core<TM,GELU,RES,PERMC>(A, B, bias, res, C, K, nvalid);
}

__global__ void __launch_bounds__(256) qkv_w(
    const float* __restrict__ A,
    const float* __restrict__ Bq, const float* __restrict__ Bk, const float* __restrict__ Bv,
    const float* __restrict__ bq, const float* __restrict__ bk, const float* __restrict__ bv,
    float* __restrict__ q, float* __restrict__ k, float* __restrict__ v)
{
    const float* B; const float* bias; float* C;
    int z = blockIdx.z;
    if (z == 0)      { B = Bq; bias = bq; C = q; }
    else if (z == 1) { B = Bk; bias = bk; C = k; }
    else             { B = Bv; bias = bv; C = v; }
    gemm_core<128,false,false,false>(A, B, bias, nullptr, C, DMODEL, DMODEL);
}

// ---- flash attention: block per (64 q-rows, h, b); 64 threads, 1 row/thread ----
// q/k/v natural layout; z written k-interleaved (A of out-proj).
__global__ void __launch_bounds__(64) flash_kernel(
    const float* __restrict__ q, const float* __restrict__ k,
    const float* __restrict__ v, float* __restrict__ z)
{
    __shared__ float Qs[64][68];
    __shared__ float Ks[32][68];
    __shared__ float Vs[32][68];
    __shared__ float Ss[64][33];
    int tid = threadIdx.x;
    int qt = blockIdx.x, h = blockIdx.y, b = blockIdx.z;
    int qi = qt*64 + tid;
    long qrow = (long)(b*SEQ + qi)*DMODEL + h*DHEAD;

    for (int r = 0; r < 64; r++)
        Qs[r][tid] = q[(long)(b*SEQ + qt*64 + r)*DMODEL + h*DHEAD + tid];

    float o[64];
    #pragma unroll
    for (int e = 0; e < 64; e++) o[e] = 0.f;
    float m = -1e30f, l = 0.f;

    int ntiles = qt*2 + 2;
    for (int kt = 0; kt < ntiles; kt++) {
        __syncthreads();
        long kb = (long)(b*SEQ + kt*32)*DMODEL + h*DHEAD;
        for (int r = 0; r < 32; r++) {
            Ks[r][tid] = k[kb + (long)r*DMODEL + tid];
            Vs[r][tid] = v[kb + (long)r*DMODEL + tid];
        }
        __syncthreads();
        for (int jg = 0; jg < 4; jg++) {
            float sa[8];
            #pragma unroll
            for (int i = 0; i < 8; i++) sa[i] = 0.f;
            for (int e4 = 0; e4 < 16; e4++) {
                float4 qv = *(const float4*)&Qs[tid][e4*4];
                #pragma unroll
                for (int i = 0; i < 8; i++) {
                    float4 kk = *(const float4*)&Ks[jg*8 + i][e4*4];
                    sa[i] += qv.x*kk.x + qv.y*kk.y + qv.z*kk.z + qv.w*kk.w;
                }
            }
            #pragma unroll
            for (int i = 0; i < 8; i++) Ss[tid][jg*8 + i] = sa[i];
        }
        float tmax = -1e30f;
        for (int j = 0; j < 32; j++) {
            int kj = kt*32 + j;
            float sv = (kj <= qi) ? Ss[tid][j]*0.125f : -1e30f;
            Ss[tid][j] = sv;
            tmax = fmaxf(tmax, sv);
        }
        float mn = fmaxf(m, tmax);
        float sc = __expf(m - mn);
        float ts = 0.f;
        for (int j = 0; j < 32; j++) {
            float p = __expf(Ss[tid][j] - mn);
            Ss[tid][j] = p;
            ts += p;
        }
        l = l*sc + ts;
        m = mn;
        #pragma unroll
        for (int e = 0; e < 64; e++) o[e] *= sc;
        for (int j = 0; j < 32; j++) {
            float p = Ss[tid][j];
            #pragma unroll
            for (int e4 = 0; e4 < 16; e4++) {
                float4 vv = *(const float4*)&Vs[j][e4*4];
                o[e4*4+0] += p*vv.x; o[e4*4+1] += p*vv.y;
                o[e4*4+2] += p*vv.z; o[e4*4+3] += p*vv.w;
            }
        }
    }
    float inv = 1.f / l;
    #pragma unroll
    for (int e = 0; e < 64; e++) z[qrow + kperm(e)] = to_tf32(o[e]*inv);
}

// smem sizes (bytes): max(3 stages, epilogue restage)
#define SMB128 (3*(128+128)*KLD*4)   // 73728 (Cs needs 67584)
#define SMB64  (3*(64+128)*KLD*4)    // 55296 (Cs needs 33792)

extern "C" void kernel_launch(void* const* d_in, const int* in_sizes, int n_in,
                              void* d_out, int out_size)
{
    const int*   tokens = (const int*)  d_in[0];
    const float* W_E    = (const float*)d_in[1];
    const float* W_pos  = (const float*)d_in[2];
    const float* ln1_w  = (const float*)d_in[3];
    const float* ln1_b  = (const float*)d_in[4];
    const float* W_Q    = (const float*)d_in[5];
    const float* b_Q    = (const float*)d_in[6];
    const float* W_K    = (const float*)d_in[7];
    const float* b_K    = (const float*)d_in[8];
    const float* W_V    = (const float*)d_in[9];
    const float* b_V    = (const float*)d_in[10];
    const float* W_O    = (const float*)d_in[11];
    const float* b_O    = (const float*)d_in[12];
    const float* ln2_w  = (const float*)d_in[13];
    const float* ln2_b  = (const float*)d_in[14];
    const float* W_in   = (const float*)d_in[15];
    const float* b_in   = (const float*)d_in[16];
    const float* W_out  = (const float*)d_in[17];
    const float* b_out  = (const float*)d_in[18];
    const float* lnf_w  = (const float*)d_in[19];
    const float* lnf_b  = (const float*)d_in[20];
    const float* W_U    = (const float*)d_in[21];
    const float* b_U    = (const float*)d_in[22];
    float* out = (float*)d_out;

    float *p_resid, *p_x, *p_q, *p_k, *p_v, *p_z, *p_h;
    float *p_bq, *p_bk, *p_bv, *p_bo, *p_bin, *p_bout, *p_bu;
    cudaGetSymbolAddress((void**)&p_resid, g_resid);
    cudaGetSymbolAddress((void**)&p_x, g_x);
    cudaGetSymbolAddress((void**)&p_q, g_q);
    cudaGetSymbolAddress((void**)&p_k, g_k);
    cudaGetSymbolAddress((void**)&p_v, g_v);
    cudaGetSymbolAddress((void**)&p_z, g_z);
    cudaGetSymbolAddress((void**)&p_h, g_h);
    cudaGetSymbolAddress((void**)&p_bq, g_bq);
    cudaGetSymbolAddress((void**)&p_bk, g_bk);
    cudaGetSymbolAddress((void**)&p_bv, g_bv);
    cudaGetSymbolAddress((void**)&p_bo, g_bo);
    cudaGetSymbolAddress((void**)&p_bin, g_bin);
    cudaGetSymbolAddress((void**)&p_bout, g_bout);
    cudaGetSymbolAddress((void**)&p_bu, g_bu);

    cudaFuncSetAttribute((const void*)gemm_w<128,false,false,false>, cudaFuncAttributeMaxDynamicSharedMemorySize, SMB128);
    cudaFuncSetAttribute((const void*)gemm_w<128,true,false,true>,   cudaFuncAttributeMaxDynamicSharedMemorySize, SMB128);
    cudaFuncSetAttribute((const void*)gemm_w<64,false,true,false>,   cudaFuncAttributeMaxDynamicSharedMemorySize, SMB64);
    cudaFuncSetAttribute((const void*)qkv_w,                         cudaFuncAttributeMaxDynamicSharedMemorySize, SMB128);

    dim3 tb(32, 8);
    trans_head<<<dim3(24, 2, LYRS*NH), tb>>>(W_Q, p_bq);
    trans_head<<<dim3(24, 2, LYRS*NH), tb>>>(W_K, p_bk);
    trans_head<<<dim3(24, 2, LYRS*NH), tb>>>(W_V, p_bv);
    trans_kn<<<dim3(24, 24, LYRS), tb>>>(W_O, p_bo, DMODEL, DMODEL, DMODEL);
    trans_kn<<<dim3(96, 24, LYRS), tb>>>(W_in, p_bin, DMODEL, DMLP, DMLP);
    trans_kn<<<dim3(24, 96, LYRS), tb>>>(W_out, p_bout, DMLP, DMODEL, DMODEL);
    trans_kn<<<dim3(NVPAD/32, 24, 1), tb>>>(W_U, p_bu, DMODEL, NVOCAB, NVPAD);

    embed_kernel<<<(MROWS*DMODEL + 255)/256, 256>>>(tokens, W_E, W_pos, p_resid);

    for (int l = 0; l < LYRS; l++) {
        layernorm_kernel<<<MROWS, 256>>>(p_resid, ln1_w + l*DMODEL, ln1_b + l*DMODEL, p_x);

        qkv_w<<<dim3(6, 16, 3), 256, SMB128>>>(
            p_x,
            p_bq + (long)l*DMODEL*DMODEL, p_bk + (long)l*DMODEL*DMODEL, p_bv + (long)l*DMODEL*DMODEL,
            b_Q + l*DMODEL, b_K + l*DMODEL, b_V + l*DMODEL,
            p_q, p_k, p_v);

        flash_kernel<<<dim3(SEQ/64, NH, BATCH), 64>>>(p_q, p_k, p_v, p_z);

        gemm_w<64,false,true,false><<<dim3(6, 32), 256, SMB64>>>(
            p_z, p_bo + (long)l*DMODEL*DMODEL, b_O + l*DMODEL, p_resid, p_resid,
            DMODEL, DMODEL);

        layernorm_kernel<<<MROWS, 256>>>(p_resid, ln2_w + l*DMODEL, ln2_b + l*DMODEL, p_x);

        gemm_w<128,true,false,true><<<dim3(24, 16), 256, SMB128>>>(
            p_x, p_bin + (long)l*DMLP*DMODEL, b_in + l*DMLP, nullptr, p_h,
            DMODEL, DMLP);

        gemm_w<64,false,true,false><<<dim3(6, 32), 256, SMB64>>>(
            p_h, p_bout + (long)l*DMODEL*DMLP, b_out + l*DMODEL, p_resid, p_resid,
            DMLP, DMODEL);
    }

    layernorm_kernel<<<MROWS, 256>>>(p_resid, lnf_w, lnf_b, p_x);

    gemm_w<128,false,false,false><<<dim3(NVPAD/128, 16), 256, SMB128>>>(
        p_x, p_bu, b_U, nullptr, out, DMODEL, NVOCAB);
}

// round 11
// speedup vs baseline: 1.5946x; 1.0113x over previous
#include <cuda_runtime.h>
#include <math.h>

#define LYRS 12
#define NH 12
#define DMODEL 768
#define DHEAD 64
#define DMLP 3072
#define NVOCAB 50257
#define NVPAD 50304
#define BATCH 2
#define SEQ 1024
#define MROWS 2048

// ---- scratch (device globals; no allocation allowed) ----
__device__ float g_resid[MROWS*DMODEL];
__device__ float g_x[MROWS*DMODEL];
__device__ float g_q[MROWS*DMODEL];
__device__ float g_k[MROWS*DMODEL];
__device__ float g_v[MROWS*DMODEL];
__device__ float g_z[MROWS*DMODEL];
__device__ float g_h[MROWS*DMLP];
// repacked K-major [N][K] tf32-rounded, k-interleaved weights
__device__ float g_bq[LYRS*DMODEL*DMODEL];
__device__ float g_bk[LYRS*DMODEL*DMODEL];
__device__ float g_bv[LYRS*DMODEL*DMODEL];
__device__ float g_bo[LYRS*DMODEL*DMODEL];
__device__ float g_bin[LYRS*DMLP*DMODEL];
__device__ float g_bout[LYRS*DMODEL*DMLP];
__device__ float g_bu[(long)NVPAD*DMODEL];

__device__ __forceinline__ float to_tf32(float x) {
    unsigned u; asm("cvt.rna.tf32.f32 %0, %1;" : "=r"(u) : "f"(x));
    return __uint_as_float(u);
}
// 16-wide k-interleave: within each 16-group, thread tig's mma operands for
// BOTH 8-k-groups are contiguous: phys = 4*t + 2*kg + hi
//   (t = c&3, hi = (c>>2)&1, kg = (c>>3)&1)
__device__ __forceinline__ int kperm(int c) {
    return (c & ~15) | ((c & 3) << 2) | (((c >> 3) & 1) << 1) | ((c >> 2) & 1);
}
__device__ __forceinline__ void cpa16(float* dst, const float* src) {
    unsigned d = (unsigned)__cvta_generic_to_shared(dst);
    asm volatile("cp.async.cg.shared.global [%0], [%1], 16;" :: "r"(d), "l"(src));
}

// ---- embedding ----
__global__ void embed_kernel(const int* __restrict__ tokens, const float* __restrict__ WE,
                             const float* __restrict__ Wpos, float* __restrict__ resid)
{
    int idx = blockIdx.x * blockDim.x + threadIdx.x;
    if (idx >= MROWS*DMODEL) return;
    int d = idx % DMODEL, bs = idx / DMODEL, s = bs % SEQ;
    resid[idx] = WE[(long)tokens[bs]*DMODEL + d] + Wpos[s*DMODEL + d];
}

// ---- layernorm: natural input, k-interleaved tf32 output ----
__global__ void layernorm_kernel(const float* __restrict__ in, const float* __restrict__ w,
                                 const float* __restrict__ b, float* __restrict__ out)
{
    __shared__ float sm[16];
    int row = blockIdx.x, tid = threadIdx.x;
    const float* x = in + (long)row * DMODEL;
    float s = 0.f, ss = 0.f;
    for (int i = tid; i < DMODEL; i += 256) { float v = x[i]; s += v; ss += v*v; }
    #pragma unroll
    for (int o = 16; o > 0; o >>= 1) {
        s  += __shfl_xor_sync(0xffffffffu, s,  o);
        ss += __shfl_xor_sync(0xffffffffu, ss, o);
    }
    if ((tid & 31) == 0) { sm[tid>>5] = s; sm[8 + (tid>>5)] = ss; }
    __syncthreads();
    if (tid < 8) {
        float a = sm[tid], c = sm[8+tid];
        #pragma unroll
        for (int o = 4; o > 0; o >>= 1) {
            a += __shfl_xor_sync(0xffu, a, o);
            c += __shfl_xor_sync(0xffu, c, o);
        }
        if (tid == 0) { sm[0] = a; sm[8] = c; }
    }
    __syncthreads();
    float mean = sm[0] * (1.f/DMODEL);
    float var  = sm[8] * (1.f/DMODEL) - mean*mean;
    float inv  = rsqrtf(var + 1e-5f);
    for (int i = tid; i < DMODEL; i += 256)
        out[(long)row*DMODEL + kperm(i)] = to_tf32((x[i]-mean)*inv*w[i] + b[i]);
}

// ---- weight repack: per-head [L][H][D][DH] -> [L][h*64+e][perm(D)] (tf32) ----
__global__ void trans_head(const float* __restrict__ src, float* __restrict__ dst)
{
    __shared__ float t[32][33];
    int tx = threadIdx.x, ty = threadIdx.y;
    int d0 = blockIdx.x*32, e0 = blockIdx.y*32, lh = blockIdx.z;
    int l = lh / NH, h = lh % NH;
    const float* sp = src + (long)lh*DMODEL*DHEAD;
    float* dp = dst + (long)l*DMODEL*DMODEL;
    #pragma unroll
    for (int i = 0; i < 4; i++)
        t[ty+8*i][tx] = sp[(long)(d0+ty+8*i)*DHEAD + e0+tx];
    __syncthreads();
    #pragma unroll
    for (int i = 0; i < 4; i++)
        dp[(long)(h*64 + e0+ty+8*i)*DMODEL + kperm(d0+tx)] = to_tf32(t[tx][ty+8*i]);
}

// ---- weight repack: [K,N] -> [Npad][perm(K)] transpose (tf32, zero pad) ----
__global__ void trans_kn(const float* __restrict__ src, float* __restrict__ dst,
                         int K, int N, int Npad)
{
    __shared__ float t[32][33];
    int tx = threadIdx.x, ty = threadIdx.y;
    int n0 = blockIdx.x*32, k0 = blockIdx.y*32, l = blockIdx.z;
    const float* sp = src + (long)l*K*N;
    float* dp = dst + (long)l*Npad*K;
    #pragma unroll
    for (int i = 0; i < 4; i++) {
        int n = n0+tx;
        t[ty+8*i][tx] = (n < N) ? sp[(long)(k0+ty+8*i)*N + n] : 0.f;
    }
    __syncthreads();
    #pragma unroll
    for (int i = 0; i < 4; i++)
        dp[(long)(n0+ty+8*i)*K + kperm(k0+tx)] = to_tf32(t[tx][ty+8*i]);
}

// ---- raw mma.sync tf32 GEMM: C[2048,nvalid] = A[2048,K] @ B[Npad,K]^T ----
// A/B stored 16-wide k-interleaved. TM x 128 tile, BK=16, 3-stage cp.async.
// KLD=16 (no pad): LDS.128 fragment loads are bank-conflict-free.
#define KLD 16
#define CLD 132

template<int TM, bool GELU, bool RES, bool PERMC>
__device__ __forceinline__ void gemm_core(
    const float* __restrict__ A, const float* __restrict__ B,
    const float* __restrict__ bias, const float* __restrict__ res,
    float* __restrict__ C, int K, int nvalid)
{
    extern __shared__ float smem[];
    const int STAGE = (TM + 128)*KLD;
    const int MF = TM/32;
    int tid = threadIdx.x, wid = tid >> 5, lane = tid & 31;
    int gid = lane >> 2, tig = lane & 3;
    int bm = blockIdx.y * TM, bn = blockIdx.x * 128;
    int wm = (wid >> 2) * (TM/2);
    int wn = (wid & 3) * 32;

    float d[TM/32][4][4];
    #pragma unroll
    for (int mi = 0; mi < MF; mi++)
        #pragma unroll
        for (int ni = 0; ni < 4; ni++)
            #pragma unroll
            for (int r = 0; r < 4; r++) d[mi][ni][r] = 0.f;

    auto loadStage = [&](int s, int it) {
        float* as = smem + s*STAGE;
        float* bs = as + TM*KLD;
        const float* Ag = A + (long)bm*K + it*16;
        const float* Bg = B + (long)bn*K + it*16;
        #pragma unroll
        for (int i = 0; i < TM/64; i++) {
            int idx = tid + 256*i;
            int row = idx >> 2, k4 = (idx & 3) << 2;
            cpa16(as + row*KLD + k4, Ag + (long)row*K + k4);
        }
        #pragma unroll
        for (int i = 0; i < 2; i++) {
            int idx = tid + 256*i;
            int row = idx >> 2, k4 = (idx & 3) << 2;
            cpa16(bs + row*KLD + k4, Bg + (long)row*K + k4);
        }
        asm volatile("cp.async.commit_group;" ::);
    };

    const int nIter = K >> 4;
    loadStage(0, 0);
    loadStage(1, 1);

    for (int it = 0; it < nIter; it++) {
        int cur = it % 3;
        if (it + 2 < nIter) asm volatile("cp.async.wait_group 1;" ::);
        else                asm volatile("cp.async.wait_group 0;" ::);
        __syncthreads();
        if (it + 2 < nIter) loadStage((it+2) % 3, it+2);

        const float* as = smem + cur*STAGE;
        const float* bs = as + TM*KLD;
        // one LDS.128 per (frag,row-half) covers BOTH k-groups
        float4 av0[TM/32], av1[TM/32], bv[4];
        #pragma unroll
        for (int mi = 0; mi < MF; mi++) {
            av0[mi] = *((const float4*)(as + (wm + mi*16 + gid)*KLD) + tig);
            av1[mi] = *((const float4*)(as + (wm + mi*16 + gid + 8)*KLD) + tig);
        }
        #pragma unroll
        for (int ni = 0; ni < 4; ni++)
            bv[ni] = *((const float4*)(bs + (wn + ni*8 + gid)*KLD) + tig);

        #pragma unroll
        for (int mi = 0; mi < MF; mi++)
            #pragma unroll
            for (int ni = 0; ni < 4; ni++) {
                float* dd = d[mi][ni];
                asm volatile(
                    "mma.sync.aligned.m16n8k8.row.col.f32.tf32.tf32.f32 "
                    "{%0,%1,%2,%3}, {%4,%5,%6,%7}, {%8,%9}, {%0,%1,%2,%3};"
                    : "+f"(dd[0]), "+f"(dd[1]), "+f"(dd[2]), "+f"(dd[3])
                    : "r"(__float_as_uint(av0[mi].x)), "r"(__float_as_uint(av1[mi].x)),
                      "r"(__float_as_uint(av0[mi].y)), "r"(__float_as_uint(av1[mi].y)),
                      "r"(__float_as_uint(bv[ni].x)), "r"(__float_as_uint(bv[ni].y)));
            }
        #pragma unroll
        for (int mi = 0; mi < MF; mi++)
            #pragma unroll
            for (int ni = 0; ni < 4; ni++) {
                float* dd = d[mi][ni];
                asm volatile(
                    "mma.sync.aligned.m16n8k8.row.col.f32.tf32.tf32.f32 "
                    "{%0,%1,%2,%3}, {%4,%5,%6,%7}, {%8,%9}, {%0,%1,%2,%3};"
                    : "+f"(dd[0]), "+f"(dd[1]), "+f"(dd[2]), "+f"(dd[3])
                    : "r"(__float_as_uint(av0[mi].z)), "r"(__float_as_uint(av1[mi].z)),
                      "r"(__float_as_uint(av0[mi].w)), "r"(__float_as_uint(av1[mi].w)),
                      "r"(__float_as_uint(bv[ni].z)), "r"(__float_as_uint(bv[ni].w)));
            }
        __syncthreads();
    }

    // epilogue: stage through smem (alias stages), then guarded fused store
    float* Cs = smem;
    #pragma unroll
    for (int mi = 0; mi < MF; mi++)
        #pragma unroll
        for (int ni = 0; ni < 4; ni++) {
            float* dd = d[mi][ni];
            int col = wn + ni*8 + 2*tig;
            float* p0 = Cs + (wm + mi*16 + gid)*CLD + col;
            float* p1 = Cs + (wm + mi*16 + gid + 8)*CLD + col;
            p0[0] = dd[0]; p0[1] = dd[1];
            p1[0] = dd[2]; p1[1] = dd[3];
        }
    __syncthreads();

    for (int idx = tid; idx < TM*128; idx += 256) {
        int r = idx >> 7, c = idx & 127;
        int n = bn + c;
        if (n < nvalid) {
            float v = Cs[r*CLD + c] + bias[n];
            long gr = bm + r;
            if (RES) v += res[gr*nvalid + n];
            if (GELU) {
                float t3 = v*v*v;
                v = 0.5f*v*(1.f + tanhf(0.7978845608028654f*(v + 0.044715f*t3)));
                v = to_tf32(v);
            }
            C[gr*nvalid + (PERMC ? kperm(n) : n)] = v;
        }
    }
}

template<int TM, bool GELU, bool RES, bool PERMC>
__global__ void __launch_bounds__(256, 2) gemm_w(
    const float* __restrict__ A, const float* __restrict__ B,
    const float* __restrict__ bias, const float* __restrict__ res,
    float* __restrict__ C, int K, int nvalid)
{
    gemm_core<TM,GELU,RES,PERMC>(A, B, bias, res, C, K, nvalid);
}

__global__ void __launch_bounds__(256, 2) qkv_w(
    const float* __restrict__ A,
    const float* __restrict__ Bq, const float* __restrict__ Bk, const float* __restrict__ Bv,
    const float* __restrict__ bq, const float* __restrict__ bk, const float* __restrict__ bv,
    float* __restrict__ q, float* __restrict__ k, float* __restrict__ v)
{
    const float* B; const float* bias; float* C;
    int z = blockIdx.z;
    if (z == 0)      { B = Bq; bias = bq; C = q; }
    else if (z == 1) { B = Bk; bias = bk; C = k; }
    else             { B = Bv; bias = bv; C = v; }
    gemm_core<128,false,false,false>(A, B, bias, nullptr, C, DMODEL, DMODEL);
}

// ---- flash attention: block per (64 q-rows, h, b); 64 threads, 1 row/thread ----
// q/k/v natural layout; z written k-interleaved (A of out-proj).
__global__ void __launch_bounds__(64) flash_kernel(
    const float* __restrict__ q, const float* __restrict__ k,
    const float* __restrict__ v, float* __restrict__ z)
{
    __shared__ float Qs[64][68];
    __shared__ float Ks[32][68];
    __shared__ float Vs[32][68];
    __shared__ float Ss[64][33];
    int tid = threadIdx.x;
    int qt = blockIdx.x, h = blockIdx.y, b = blockIdx.z;
    int qi = qt*64 + tid;
    long qrow = (long)(b*SEQ + qi)*DMODEL + h*DHEAD;

    for (int r = 0; r < 64; r++)
        Qs[r][tid] = q[(long)(b*SEQ + qt*64 + r)*DMODEL + h*DHEAD + tid];

    float o[64];
    #pragma unroll
    for (int e = 0; e < 64; e++) o[e] = 0.f;
    float m = -1e30f, l = 0.f;

    int ntiles = qt*2 + 2;
    for (int kt = 0; kt < ntiles; kt++) {
        __syncthreads();
        long kb = (long)(b*SEQ + kt*32)*DMODEL + h*DHEAD;
        for (int r = 0; r < 32; r++) {
            Ks[r][tid] = k[kb + (long)r*DMODEL + tid];
            Vs[r][tid] = v[kb + (long)r*DMODEL + tid];
        }
        __syncthreads();
        for (int jg = 0; jg < 4; jg++) {
            float sa[8];
            #pragma unroll
            for (int i = 0; i < 8; i++) sa[i] = 0.f;
            for (int e4 = 0; e4 < 16; e4++) {
                float4 qv = *(const float4*)&Qs[tid][e4*4];
                #pragma unroll
                for (int i = 0; i < 8; i++) {
                    float4 kk = *(const float4*)&Ks[jg*8 + i][e4*4];
                    sa[i] += qv.x*kk.x + qv.y*kk.y + qv.z*kk.z + qv.w*kk.w;
                }
            }
            #pragma unroll
            for (int i = 0; i < 8; i++) Ss[tid][jg*8 + i] = sa[i];
        }
        float tmax = -1e30f;
        for (int j = 0; j < 32; j++) {
            int kj = kt*32 + j;
            float sv = (kj <= qi) ? Ss[tid][j]*0.125f : -1e30f;
            Ss[tid][j] = sv;
            tmax = fmaxf(tmax, sv);
        }
        float mn = fmaxf(m, tmax);
        float sc = __expf(m - mn);
        float ts = 0.f;
        for (int j = 0; j < 32; j++) {
            float p = __expf(Ss[tid][j] - mn);
            Ss[tid][j] = p;
            ts += p;
        }
        l = l*sc + ts;
        m = mn;
        #pragma unroll
        for (int e = 0; e < 64; e++) o[e] *= sc;
        for (int j = 0; j < 32; j++) {
            float p = Ss[tid][j];
            #pragma unroll
            for (int e4 = 0; e4 < 16; e4++) {
                float4 vv = *(const float4*)&Vs[j][e4*4];
                o[e4*4+0] += p*vv.x; o[e4*4+1] += p*vv.y;
                o[e4*4+2] += p*vv.z; o[e4*4+3] += p*vv.w;
            }
        }
    }
    float inv = 1.f / l;
    #pragma unroll
    for (int e = 0; e < 64; e++) z[qrow + kperm(e)] = to_tf32(o[e]*inv);
}

// smem sizes (bytes): max(3 stages, epilogue restage)
#define SMB128 (128*CLD*4)                       // 67584 (stages need 49152)
#define SMB64  (3*(64+128)*KLD*4 > 64*CLD*4 ? 3*(64+128)*KLD*4 : 64*CLD*4)  // 36864

extern "C" void kernel_launch(void* const* d_in, const int* in_sizes, int n_in,
                              void* d_out, int out_size)
{
    const int*   tokens = (const int*)  d_in[0];
    const float* W_E    = (const float*)d_in[1];
    const float* W_pos  = (const float*)d_in[2];
    const float* ln1_w  = (const float*)d_in[3];
    const float* ln1_b  = (const float*)d_in[4];
    const float* W_Q    = (const float*)d_in[5];
    const float* b_Q    = (const float*)d_in[6];
    const float* W_K    = (const float*)d_in[7];
    const float* b_K    = (const float*)d_in[8];
    const float* W_V    = (const float*)d_in[9];
    const float* b_V    = (const float*)d_in[10];
    const float* W_O    = (const float*)d_in[11];
    const float* b_O    = (const float*)d_in[12];
    const float* ln2_w  = (const float*)d_in[13];
    const float* ln2_b  = (const float*)d_in[14];
    const float* W_in   = (const float*)d_in[15];
    const float* b_in   = (const float*)d_in[16];
    const float* W_out  = (const float*)d_in[17];
    const float* b_out  = (const float*)d_in[18];
    const float* lnf_w  = (const float*)d_in[19];
    const float* lnf_b  = (const float*)d_in[20];
    const float* W_U    = (const float*)d_in[21];
    const float* b_U    = (const float*)d_in[22];
    float* out = (float*)d_out;

    float *p_resid, *p_x, *p_q, *p_k, *p_v, *p_z, *p_h;
    float *p_bq, *p_bk, *p_bv, *p_bo, *p_bin, *p_bout, *p_bu;
    cudaGetSymbolAddress((void**)&p_resid, g_resid);
    cudaGetSymbolAddress((void**)&p_x, g_x);
    cudaGetSymbolAddress((void**)&p_q, g_q);
    cudaGetSymbolAddress((void**)&p_k, g_k);
    cudaGetSymbolAddress((void**)&p_v, g_v);
    cudaGetSymbolAddress((void**)&p_z, g_z);
    cudaGetSymbolAddress((void**)&p_h, g_h);
    cudaGetSymbolAddress((void**)&p_bq, g_bq);
    cudaGetSymbolAddress((void**)&p_bk, g_bk);
    cudaGetSymbolAddress((void**)&p_bv, g_bv);
    cudaGetSymbolAddress((void**)&p_bo, g_bo);
    cudaGetSymbolAddress((void**)&p_bin, g_bin);
    cudaGetSymbolAddress((void**)&p_bout, g_bout);
    cudaGetSymbolAddress((void**)&p_bu, g_bu);

    cudaFuncSetAttribute((const void*)gemm_w<128,false,false,false>, cudaFuncAttributeMaxDynamicSharedMemorySize, SMB128);
    cudaFuncSetAttribute((const void*)gemm_w<128,true,false,true>,   cudaFuncAttributeMaxDynamicSharedMemorySize, SMB128);
    cudaFuncSetAttribute((const void*)gemm_w<64,false,true,false>,   cudaFuncAttributeMaxDynamicSharedMemorySize, SMB64);
    cudaFuncSetAttribute((const void*)qkv_w,                         cudaFuncAttributeMaxDynamicSharedMemorySize, SMB128);

    dim3 tb(32, 8);
    trans_head<<<dim3(24, 2, LYRS*NH), tb>>>(W_Q, p_bq);
    trans_head<<<dim3(24, 2, LYRS*NH), tb>>>(W_K, p_bk);
    trans_head<<<dim3(24, 2, LYRS*NH), tb>>>(W_V, p_bv);
    trans_kn<<<dim3(24, 24, LYRS), tb>>>(W_O, p_bo, DMODEL, DMODEL, DMODEL);
    trans_kn<<<dim3(96, 24, LYRS), tb>>>(W_in, p_bin, DMODEL, DMLP, DMLP);
    trans_kn<<<dim3(24, 96, LYRS), tb>>>(W_out, p_bout, DMLP, DMODEL, DMODEL);
    trans_kn<<<dim3(NVPAD/32, 24, 1), tb>>>(W_U, p_bu, DMODEL, NVOCAB, NVPAD);

    embed_kernel<<<(MROWS*DMODEL + 255)/256, 256>>>(tokens, W_E, W_pos, p_resid);

    for (int l = 0; l < LYRS; l++) {
        layernorm_kernel<<<MROWS, 256>>>(p_resid, ln1_w + l*DMODEL, ln1_b + l*DMODEL, p_x);

        qkv_w<<<dim3(6, 16, 3), 256, SMB128>>>(
            p_x,
            p_bq + (long)l*DMODEL*DMODEL, p_bk + (long)l*DMODEL*DMODEL, p_bv + (long)l*DMODEL*DMODEL,
            b_Q + l*DMODEL, b_K + l*DMODEL, b_V + l*DMODEL,
            p_q, p_k, p_v);

        flash_kernel<<<dim3(SEQ/64, NH, BATCH), 64>>>(p_q, p_k, p_v, p_z);

        gemm_w<64,false,true,false><<<dim3(6, 32), 256, SMB64>>>(
            p_z, p_bo + (long)l*DMODEL*DMODEL, b_O + l*DMODEL, p_resid, p_resid,
            DMODEL, DMODEL);

        layernorm_kernel<<<MROWS, 256>>>(p_resid, ln2_w + l*DMODEL, ln2_b + l*DMODEL, p_x);

        gemm_w<128,true,false,true><<<dim3(24, 16), 256, SMB128>>>(
            p_x, p_bin + (long)l*DMLP*DMODEL, b_in + l*DMLP, nullptr, p_h,
            DMODEL, DMLP);

        gemm_w<64,false,true,false><<<dim3(6, 32), 256, SMB64>>>(
            p_h, p_bout + (long)l*DMODEL*DMLP, b_out + l*DMODEL, p_resid, p_resid,
            DMLP, DMODEL);
    }

    layernorm_kernel<<<MROWS, 256>>>(p_resid, lnf_w, lnf_b, p_x);

    gemm_w<128,false,false,false><<<dim3(NVPAD/128, 16), 256, SMB128>>>(
        p_x, p_bu, b_U, nullptr, out, DMODEL, NVOCAB);
}